// round 14
// baseline (speedup 1.0000x reference)
#include <cuda_runtime.h>
#include <cuda_fp16.h>
#include <math.h>
#include <stdint.h>

// ---------------- constants ----------------
#define BATCH   2
#define SEQLEN  4096
#define BL      (BATCH*SEQLEN)          // 8192 rows
#define DM      768
#define DI      1536
#define NH      24
#define HD      64
#define DS      64
#define DCONV   7
#define CONVD   (DI + 2*DS)             // 1664
#define DIP     (2*DI + 2*DS + 2*NH)    // 3248
#define CHUNK_T 256
#define NC      (SEQLEN/CHUNK_T)        // 16
#define NBB     (2*BATCH)               // 4 direction-batches
#define EPSV    1e-5f
#define WCONV_BLKS ((DIP*DM + 255)/256) // 9744

// ---------------- scratch ----------------
__device__ __half g_zxh[(size_t)BL*DIP];
__device__ __half g_xch[(size_t)BL*CONVD];
__device__ float g_dt[(size_t)NBB*SEQLEN*NH];
__device__ float g_acum[(size_t)NBB*NH*NC*CHUNK_T];
__device__ float g_csum[(size_t)NBB*NH*NC];
__device__ float g_states[(size_t)NBB*NC*NH*HD*DS];
__device__ __half g_prevh[(size_t)NBB*NC*NH*HD*DS];
__device__ __half g_yssdh[(size_t)NBB*SEQLEN*DI];
__device__ float g_dterm[(size_t)BL*NH];
__device__ __half g_uh[(size_t)BL*DM];
__device__ __half g_ynh[(size_t)BL*DI];
__device__ __half g_wah[(size_t)DIP*DM];
__device__ __half g_woh[(size_t)DM*DI];

// ---------------- helpers ----------------
__device__ __forceinline__ float softplusf(float x){
    return (x > 20.f) ? x : log1pf(expf(x));
}
__device__ __forceinline__ float siluf(float x){
    return x / (1.f + expf(-x));
}
#define MMA_F16(acc, a, b) \
    asm volatile("mma.sync.aligned.m16n8k16.row.col.f32.f16.f16.f32 " \
        "{%0,%1,%2,%3},{%4,%5,%6,%7},{%8,%9},{%0,%1,%2,%3};" \
        : "+f"(acc[0]),"+f"(acc[1]),"+f"(acc[2]),"+f"(acc[3]) \
        : "r"(a[0]),"r"(a[1]),"r"(a[2]),"r"(a[3]),"r"(b[0]),"r"(b[1]))

__device__ __forceinline__ void ldsm4(unsigned* r, const __half* p){
    unsigned a = (unsigned)__cvta_generic_to_shared(p);
    asm volatile("ldmatrix.sync.aligned.m8n8.x4.shared.b16 {%0,%1,%2,%3}, [%4];"
        : "=r"(r[0]),"=r"(r[1]),"=r"(r[2]),"=r"(r[3]) : "r"(a));
}

__device__ __forceinline__ void cp16(void* dst, const void* src, bool p){
    unsigned d = (unsigned)__cvta_generic_to_shared(dst);
    int sz = p ? 16 : 0;
    asm volatile("cp.async.cg.shared.global [%0], [%1], 16, %2;\n"
                 :: "r"(d), "l"(src), "r"(sz));
}
__device__ __forceinline__ void cp_commit(){ asm volatile("cp.async.commit_group;\n"); }
__device__ __forceinline__ void cp_wait2(){ asm volatile("cp.async.wait_group 2;\n"); }

__device__ __forceinline__ float blockReduce256(float v, float* red){
    int tid = threadIdx.x;
    int lane = tid & 31, w = tid >> 5;
    #pragma unroll
    for (int o = 16; o > 0; o >>= 1) v += __shfl_xor_sync(0xffffffffu, v, o);
    if (lane == 0) red[w] = v;
    __syncthreads();
    float r = (lane < 8) ? red[lane] : 0.f;
    #pragma unroll
    for (int o = 4; o > 0; o >>= 1) r += __shfl_xor_sync(0xffffffffu, r, o);
    r = __shfl_sync(0xffffffffu, r, 0);
    return r;
}

// ---------------- 0+1) fused weight-convert + LayerNorm ----------------
__global__ void prep_kernel(const float* __restrict__ wi,
                            const float* __restrict__ wo,
                            const float* __restrict__ x,
                            const float* __restrict__ lw,
                            const float* __restrict__ lb){
    if (blockIdx.x < WCONV_BLKS){
        int i = blockIdx.x*256 + threadIdx.x;
        if (i < DIP*DM) g_wah[i] = __float2half(wi[i]);
        if (i < DM*DI)  g_woh[i] = __float2half(wo[i]);
        return;
    }
    __shared__ float red[8];
    int row = blockIdx.x - WCONV_BLKS;
    const float* xr = x + (size_t)row*DM;
    int tid = threadIdx.x;
    float s = 0.f;
    for (int i = tid; i < DM; i += 256) s += xr[i];
    float mu = blockReduce256(s, red) / DM;
    __syncthreads();
    float v = 0.f;
    for (int i = tid; i < DM; i += 256){ float d = xr[i]-mu; v += d*d; }
    float var = blockReduce256(v, red) / DM;
    float inv = rsqrtf(var + EPSV);
    for (int i = tid; i < DM; i += 256)
        g_uh[(size_t)row*DM + i] = __float2half((xr[i]-mu)*inv*lw[i] + lb[i]);
}

// ---------------- fp16 GEMM, 4-stage cp.async, m16n8k16, ldmatrix ----------
#define SMSH 40
#define GSTH 4
__global__ __launch_bounds__(256, 2)
void gemm_h(const __half* __restrict__ A, int lda,
            const __half* __restrict__ B, int ldb,
            const float* __restrict__ R,
            float* __restrict__ C, __half* __restrict__ Ch, int ldc,
            int M, int N, int K){
    extern __shared__ __half smh[];
    __half* AsB = smh;
    __half* BsB = smh + GSTH*128*SMSH;
    const int tid  = threadIdx.x;
    const int lane = tid & 31;
    const int warp = tid >> 5;
    const int wm = warp >> 2;
    const int wn = warp & 3;
    const int m0 = blockIdx.y * 128;
    const int n0 = blockIdx.x * 128;
    const int rowsel = lane & 15;
    const int koffA  = (lane >> 4) * 8;
    const int nsel   = (lane & 7) + ((lane >> 4) * 8);
    const int koffB  = ((lane >> 3) & 1) * 8;

    float acc[4][4][4];
    #pragma unroll
    for (int i=0;i<4;i++)
        #pragma unroll
        for (int j=0;j<4;j++)
            #pragma unroll
            for (int r=0;r<4;r++) acc[i][j][r]=0.f;

    const int nk = K >> 5;
    const int c0r = tid >> 2,  c0q = tid & 3;
    const int c1r = (tid+256) >> 2, c1q = tid & 3;

    const __half* ApA = A + (size_t)(m0 + c0r)*lda + c0q*8;
    const __half* ApB = A + (size_t)(m0 + c1r)*lda + c1q*8;
    const int bn0 = n0 + c0r, bn1 = n0 + c1r;
    const __half* BpA = B + (size_t)bn0*ldb + c0q*8;
    const __half* BpB = B + (size_t)bn1*ldb + c1q*8;
    const bool bokA = bn0 < N, bokB = bn1 < N;

    #pragma unroll
    for (int s = 0; s < GSTH-1; s++){
        int ko = s << 5;
        __half* as = AsB + s*(128*SMSH);
        __half* bs = BsB + s*(128*SMSH);
        cp16(as + c0r*SMSH + c0q*8, ApA + ko, true);
        cp16(as + c1r*SMSH + c1q*8, ApB + ko, true);
        cp16(bs + c0r*SMSH + c0q*8, BpA + ko, bokA);
        cp16(bs + c1r*SMSH + c1q*8, BpB + ko, bokB);
        cp_commit();
    }

    for (int kt = 0; kt < nk; kt++){
        cp_wait2();
        __syncthreads();
        int kn = kt + GSTH - 1;
        if (kn < nk){
            int ko = kn << 5;
            int stg = kn % GSTH;
            __half* as = AsB + stg*(128*SMSH);
            __half* bs = BsB + stg*(128*SMSH);
            cp16(as + c0r*SMSH + c0q*8, ApA + ko, true);
            cp16(as + c1r*SMSH + c1q*8, ApB + ko, true);
            cp16(bs + c0r*SMSH + c0q*8, BpA + ko, bokA);
            cp16(bs + c1r*SMSH + c1q*8, BpB + ko, bokB);
        }
        cp_commit();

        const __half* As = AsB + (kt % GSTH)*(128*SMSH);
        const __half* Bs = BsB + (kt % GSTH)*(128*SMSH);
        #pragma unroll
        for (int ks = 0; ks < 32; ks += 16){
            unsigned a[4][4], bfr[4][2];
            #pragma unroll
            for (int i=0;i<4;i++)
                ldsm4(a[i], As + (wm*64 + i*16 + rowsel)*SMSH + ks + koffA);
            {
                unsigned t0[4], t1[4];
                ldsm4(t0, Bs + (wn*32 + nsel)*SMSH + ks + koffB);
                ldsm4(t1, Bs + (wn*32 + 16 + nsel)*SMSH + ks + koffB);
                bfr[0][0]=t0[0]; bfr[0][1]=t0[1]; bfr[1][0]=t0[2]; bfr[1][1]=t0[3];
                bfr[2][0]=t1[0]; bfr[2][1]=t1[1]; bfr[3][0]=t1[2]; bfr[3][1]=t1[3];
            }
            #pragma unroll
            for (int i=0;i<4;i++)
                #pragma unroll
                for (int j=0;j<4;j++) MMA_F16(acc[i][j], a[i], bfr[j]);
        }
    }

    #pragma unroll
    for (int i=0;i<4;i++){
        int r0 = m0 + wm*64 + i*16 + (lane>>2);
        #pragma unroll
        for (int j=0;j<4;j++){
            int cb = n0 + wn*32 + j*8;
            if (cb < N){
                int cc = cb + 2*(lane & 3);
                size_t o0 = (size_t)r0*ldc + cc;
                size_t o1 = (size_t)(r0+8)*ldc + cc;
                if (Ch){
                    *(__half2*)&Ch[o0] = __floats2half2_rn(acc[i][j][0], acc[i][j][1]);
                    *(__half2*)&Ch[o1] = __floats2half2_rn(acc[i][j][2], acc[i][j][3]);
                } else {
                    float v0 = acc[i][j][0], v1 = acc[i][j][1];
                    float v2 = acc[i][j][2], v3 = acc[i][j][3];
                    if (R){ v0 += R[o0]; v1 += R[o0+1]; v2 += R[o1]; v3 += R[o1+1]; }
                    C[o0] = v0; C[o0+1] = v1; C[o1] = v2; C[o1+1] = v3;
                }
            }
        }
    }
}

// ---------------- fp16 GEMM, 128xM x 64xN tile (out_proj + residual) -------
__global__ __launch_bounds__(256, 2)
void gemm_h_n64(const __half* __restrict__ A, int lda,
                const __half* __restrict__ B, int ldb,
                const float* __restrict__ R,
                float* __restrict__ C, int ldc,
                int M, int N, int K){
    extern __shared__ __half smh[];
    __half* AsB = smh;
    __half* BsB = smh + GSTH*128*SMSH;
    const int tid  = threadIdx.x;
    const int lane = tid & 31;
    const int warp = tid >> 5;
    const int wm = warp >> 2;
    const int wn = warp & 3;
    const int m0 = blockIdx.y * 128;
    const int n0 = blockIdx.x * 64;
    const int rowsel = lane & 15;
    const int koffA  = (lane >> 4) * 8;
    const int nsel   = (lane & 7) + ((lane >> 4) * 8);
    const int koffB  = ((lane >> 3) & 1) * 8;

    float acc[4][2][4];
    #pragma unroll
    for (int i=0;i<4;i++)
        #pragma unroll
        for (int j=0;j<2;j++)
            #pragma unroll
            for (int r=0;r<4;r++) acc[i][j][r]=0.f;

    const int nk = K >> 5;
    const int c0r = tid >> 2,  c0q = tid & 3;
    const int c1r = (tid+256) >> 2, c1q = tid & 3;

    const __half* ApA = A + (size_t)(m0 + c0r)*lda + c0q*8;
    const __half* ApB = A + (size_t)(m0 + c1r)*lda + c1q*8;
    const __half* Bp  = B + (size_t)(n0 + c0r)*ldb + c0q*8;
    const bool brow = c0r < 64;

    #pragma unroll
    for (int s = 0; s < GSTH-1; s++){
        int ko = s << 5;
        __half* as = AsB + s*(128*SMSH);
        __half* bs = BsB + s*(64*SMSH);
        cp16(as + c0r*SMSH + c0q*8, ApA + ko, true);
        cp16(as + c1r*SMSH + c1q*8, ApB + ko, true);
        if (brow) cp16(bs + c0r*SMSH + c0q*8, Bp + ko, true);
        cp_commit();
    }

    for (int kt = 0; kt < nk; kt++){
        cp_wait2();
        __syncthreads();
        int kn = kt + GSTH - 1;
        if (kn < nk){
            int ko = kn << 5;
            int stg = kn % GSTH;
            __half* as = AsB + stg*(128*SMSH);
            __half* bs = BsB + stg*(64*SMSH);
            cp16(as + c0r*SMSH + c0q*8, ApA + ko, true);
            cp16(as + c1r*SMSH + c1q*8, ApB + ko, true);
            if (brow) cp16(bs + c0r*SMSH + c0q*8, Bp + ko, true);
        }
        cp_commit();

        const __half* As = AsB + (kt % GSTH)*(128*SMSH);
        const __half* Bs = BsB + (kt % GSTH)*(64*SMSH);
        #pragma unroll
        for (int ks = 0; ks < 32; ks += 16){
            unsigned a[4][4], bfr[2][2];
            #pragma unroll
            for (int i=0;i<4;i++)
                ldsm4(a[i], As + (wm*64 + i*16 + rowsel)*SMSH + ks + koffA);
            {
                unsigned t0[4];
                ldsm4(t0, Bs + (wn*16 + nsel)*SMSH + ks + koffB);
                bfr[0][0]=t0[0]; bfr[0][1]=t0[1]; bfr[1][0]=t0[2]; bfr[1][1]=t0[3];
            }
            #pragma unroll
            for (int i=0;i<4;i++)
                #pragma unroll
                for (int j=0;j<2;j++) MMA_F16(acc[i][j], a[i], bfr[j]);
        }
    }

    #pragma unroll
    for (int i=0;i<4;i++){
        int r0 = m0 + wm*64 + i*16 + (lane>>2);
        #pragma unroll
        for (int j=0;j<2;j++){
            int cc = n0 + wn*16 + j*8 + 2*(lane & 3);
            size_t o0 = (size_t)r0*ldc + cc;
            size_t o1 = (size_t)(r0+8)*ldc + cc;
            float v0 = acc[i][j][0], v1 = acc[i][j][1];
            float v2 = acc[i][j][2], v3 = acc[i][j][3];
            if (R){ v0 += R[o0]; v1 += R[o0+1]; v2 += R[o1]; v3 += R[o1+1]; }
            C[o0] = v0; C[o0+1] = v1; C[o1] = v2; C[o1+1] = v3;
        }
    }
}

// ---------------- 4) conv: half2 channel pairs ----------------
#define CTS 32
__global__ void conv_kernel(const float* __restrict__ cw,
                            const float* __restrict__ cb){
    __shared__ __half2 s[CTS+6][64];
    __shared__ __half2 w[7][64];
    __shared__ __half2 bias[64];
    int ch0 = blockIdx.x * 128;
    int t0  = blockIdx.y * CTS;
    int b   = blockIdx.z;
    int tid = threadIdx.x;
    for (int i = tid; i < 7*64; i += 256){
        int j = i >> 6, cp = i & 63;
        w[j][cp] = __floats2half2_rn(cw[(size_t)(ch0+cp*2)*DCONV + j],
                                     cw[(size_t)(ch0+cp*2+1)*DCONV + j]);
    }
    if (tid < 64) bias[tid] = __floats2half2_rn(cb[ch0 + tid*2], cb[ch0 + tid*2+1]);
    for (int i = tid; i < (CTS+6)*64; i += 256){
        int tt = t0 - 6 + (i >> 6);
        int cp = i & 63;
        s[i>>6][cp] = (tt >= 0)
            ? *(const __half2*)&g_zxh[(size_t)(b*SEQLEN + tt)*DIP + DI + ch0 + cp*2]
            : __floats2half2_rn(0.f, 0.f);
    }
    __syncthreads();
    #pragma unroll
    for (int k = 0; k < 8; k++){
        int o = tid + k*256;
        int tl = o >> 6, cp = o & 63;
        float2 acc = __half22float2(bias[cp]);
        #pragma unroll
        for (int j = 0; j < 7; j++){
            float2 wv = __half22float2(w[j][cp]);
            float2 sv = __half22float2(s[tl+j][cp]);
            acc.x += wv.x*sv.x; acc.y += wv.y*sv.y;
        }
        *(__half2*)&g_xch[(size_t)(b*SEQLEN + t0 + tl)*CONVD + ch0 + cp*2]
            = __floats2half2_rn(siluf(acc.x), siluf(acc.y));
    }
}

// ---------------- 5) dt softplus + per-chunk cumsum (shfl scan) ------------
__global__ void cumsum_kernel(const float* __restrict__ A_log,
                              const float* __restrict__ dt_bias){
    int bid = blockIdx.x;            // ((bb*NH)+h)*NC + c
    int c = bid % NC;
    int h = (bid / NC) % NH;
    int bb = bid / (NC*NH);
    int b = bb & 1;
    bool rev = bb >= 2;
    int tid = threadIdx.x;
    int lane = tid & 31, warp = tid >> 5;
    float a = -expf(A_log[h]);
    int t = c*CHUNK_T + tid;
    int tg = rev ? (SEQLEN-1-t) : t;
    int col = (DIP - 2*NH) + (rev ? NH + h : h);
    float raw = __half2float(g_zxh[(size_t)(b*SEQLEN + tg)*DIP + col]);
    float dtv = softplusf(raw + dt_bias[h]);
    g_dt[(size_t)(bb*SEQLEN + t)*NH + h] = dtv;
    float v = dtv * a;
    float sc = v;
    #pragma unroll
    for (int o = 1; o < 32; o <<= 1){
        float u = __shfl_up_sync(0xffffffffu, sc, o);
        if (lane >= o) sc += u;
    }
    __shared__ float wsum[8];
    if (lane == 31) wsum[warp] = sc;
    __syncthreads();
    if (warp == 0 && lane < 8){
        float ws = wsum[lane];
        #pragma unroll
        for (int o = 1; o < 8; o <<= 1){
            float u = __shfl_up_sync(0xffu, ws, o);
            if (lane >= o) ws += u;
        }
        wsum[lane] = ws;
    }
    __syncthreads();
    float base = (warp > 0) ? wsum[warp-1] : 0.f;
    float total = sc + base;
    g_acum[(size_t)bid*CHUNK_T + tid] = total;
    if (tid == CHUNK_T-1) g_csum[bid] = total;
}

// ---------------- 6+9) fused chunk-states + fc_D ----------------
#define SMH 88
#define NSTATES (NBB*NC*NH)            // 1536
__global__ void states_fcd_kernel(const float* __restrict__ fw){
    __shared__ __align__(16) char smem_u[23040];
    int tid = threadIdx.x;

    if (blockIdx.x >= NSTATES){
        // ---- fc_D part ----
        float (*ws)[132] = (float(*)[132])smem_u;   // 24*132*4 = 12672 B
        int r0 = (blockIdx.x - NSTATES) * 64;
        int rl = tid >> 2;
        int lj = tid & 3;
        float acc[6] = {0.f,0.f,0.f,0.f,0.f,0.f};
        for (int k0 = 0; k0 < DI; k0 += 128){
            for (int i = tid; i < NH*128; i += 256)
                ws[i>>7][i&127] = fw[(size_t)(i>>7)*DI + k0 + (i&127)];
            __syncthreads();
            const __half2* xr = (const __half2*)&g_xch[(size_t)(r0+rl)*CONVD + k0];
            #pragma unroll 16
            for (int kk = 0; kk < 64; kk += 2){
                float2 x0 = __half22float2(xr[kk]);
                float2 x1 = __half22float2(xr[kk+1]);
                #pragma unroll
                for (int hh = 0; hh < 6; hh++){
                    int h = lj*6 + hh;
                    acc[hh] += x0.x*ws[h][kk*2] + x0.y*ws[h][kk*2+1]
                             + x1.x*ws[h][kk*2+2] + x1.y*ws[h][kk*2+3];
                }
            }
            __syncthreads();
        }
        #pragma unroll
        for (int hh = 0; hh < 6; hh++)
            g_dterm[(size_t)(r0+rl)*NH + lj*6 + hh] = acc[hh];
        return;
    }

    // ---- states part ----
    __half* Ab = (__half*)smem_u;                   // 64*SMH*2 = 11264 B
    __half* Bb = Ab + 64*SMH;                       // 11264 B
    float* dtl  = (float*)(smem_u + 22528);         // 256 B
    float* decl = (float*)(smem_u + 22784);         // 256 B

    int bid = blockIdx.x;
    int h = bid % NH;
    int c = (bid / NH) % NC;
    int bb = bid / (NH*NC);
    int b = bb & 1;
    bool rev = bb >= 2;
    int lane = tid & 31, warp = tid >> 5;
    int wm = warp >> 2, wn = warp & 3;
    int gid = lane >> 2, qid = lane & 3;
    const int rowsel = lane & 15;
    const int koffA  = (lane >> 4) * 8;
    const int nsel   = (lane & 7) + ((lane >> 4) * 8);
    const int koffB  = ((lane >> 3) & 1) * 8;

    const float* ac = g_acum + ((size_t)(bb*NH + h)*NC + c)*CHUNK_T;
    float cs = g_csum[(bb*NH + h)*NC + c];

    float acc[2][2][4];
    #pragma unroll
    for (int i=0;i<2;i++)
        #pragma unroll
        for (int j=0;j<2;j++)
            #pragma unroll
            for (int r=0;r<4;r++) acc[i][j][r]=0.f;

    for (int ltile = 0; ltile < 4; ltile++){
        if (tid < 64){
            int lc2 = ltile*64 + tid;
            int tgl = c*CHUNK_T + lc2;
            dtl[tid] = g_dt[(size_t)(bb*SEQLEN + tgl)*NH + h];
            decl[tid] = expf(cs - ac[lc2]);
        }
        __syncthreads();
        for (int idx = tid; idx < 64*64; idx += 256){
            int l = idx >> 6, q = idx & 63;
            int tgl = c*CHUNK_T + ltile*64 + l;
            int trow = rev ? (SEQLEN-1 - tgl) : tgl;
            size_t roff = (size_t)(b*SEQLEN + trow)*CONVD;
            float xv = __half2float(g_xch[roff + h*HD + q]);
            float bv = __half2float(g_xch[roff + DI + q]);
            Ab[q*SMH + l] = __float2half(xv * dtl[l]);
            Bb[q*SMH + l] = __float2half(bv * decl[l]);
        }
        __syncthreads();
        #pragma unroll
        for (int ks = 0; ks < 64; ks += 16){
            unsigned a[2][4], bf[2][2];
            #pragma unroll
            for (int i=0;i<2;i++)
                ldsm4(a[i], Ab + (wm*32 + i*16 + rowsel)*SMH + ks + koffA);
            {
                unsigned t0[4];
                ldsm4(t0, Bb + (wn*16 + nsel)*SMH + ks + koffB);
                bf[0][0]=t0[0]; bf[0][1]=t0[1]; bf[1][0]=t0[2]; bf[1][1]=t0[3];
            }
            #pragma unroll
            for (int i=0;i<2;i++)
                #pragma unroll
                for (int j=0;j<2;j++) MMA_F16(acc[i][j], a[i], bf[j]);
        }
        __syncthreads();
    }
    float* sp = g_states + (size_t)bid*(HD*DS);
    #pragma unroll
    for (int i=0;i<2;i++){
        int p = wm*32 + i*16 + gid;
        #pragma unroll
        for (int j=0;j<2;j++){
            int n = wn*16 + j*8 + 2*qid;
            sp[p*DS + n]     = acc[i][j][0];
            sp[p*DS + n + 1] = acc[i][j][1];
            sp[(p+8)*DS + n]     = acc[i][j][2];
            sp[(p+8)*DS + n + 1] = acc[i][j][3];
        }
    }
}

// ---------------- 7) inter-chunk scan (4-way split) ----------------
__global__ void prevscan_kernel(){
    int bid = blockIdx.x;
    int part = bid & 3;
    int bh = bid >> 2;
    int bb = bh / NH, h = bh % NH;
    int tid = threadIdx.x;
    int base = part*1024 + tid;
    float run[4];
    #pragma unroll
    for (int k = 0; k < 4; k++) run[k] = 0.f;
    for (int c = 0; c < NC; c++){
        size_t off = ((size_t)(bb*NC + c)*NH + h)*(HD*DS);
        float e = expf(g_csum[bh*NC + c]);
        #pragma unroll
        for (int k = 0; k < 4; k++){
            int idx = base + k*256;
            g_prevh[off + idx] = __float2half(run[k]);
            run[k] = run[k]*e + g_states[off + idx];
        }
    }
}

// ---------------- 8) Y = Y_diag + Y_off (fp16 mma + ldmatrix) --------------
__global__ void ydiag_kernel(){
    int bid = blockIdx.x;            // ((bb*NC+c)*NH+h)*4 + lt
    int lt = bid & 3;
    int h  = (bid >> 2) % NH;
    int c  = (bid / (4*NH)) % NC;
    int bb = bid / (4*NH*NC);
    int b = bb & 1;
    bool rev = bb >= 2;
    int tid = threadIdx.x;
    int lane = tid & 31, warp = tid >> 5;
    int wm = warp >> 2, wn = warp & 3;
    int gid = lane >> 2, qid = lane & 3;
    const int rowsel = lane & 15;
    const int koffA  = (lane >> 4) * 8;
    const int nsel   = (lane & 7) + ((lane >> 4) * 8);
    const int koffB  = ((lane >> 3) & 1) * 8;

    __shared__ __half Ab[64*SMH];
    __shared__ __half Bb[64*SMH];
    __shared__ float acl[64], eacl[64], acs[64], dts[64];

    const float* ac = g_acum + ((size_t)(bb*NH + h)*NC + c)*CHUNK_T;

    if (tid < 64){
        float v = ac[lt*64 + tid];
        acl[tid] = v;
        eacl[tid] = expf(v);
    }
    __syncthreads();

    float acc[2][2][4];
    #pragma unroll
    for (int i=0;i<2;i++)
        #pragma unroll
        for (int j=0;j<2;j++)
            #pragma unroll
            for (int r=0;r<4;r++) acc[i][j][r]=0.f;

    // ---- Y_off with UNSCALED C (scale acc rows afterwards)
    {
        size_t poff = ((size_t)(bb*NC + c)*NH + h)*(HD*DS);
        for (int i2 = tid; i2 < 2048; i2 += 256){
            int l = i2 >> 5, c2 = (i2 & 31) * 2;
            int tgl = c*CHUNK_T + lt*64 + l;
            int trl = rev ? (SEQLEN-1 - tgl) : tgl;
            *(__half2*)&Ab[l*SMH + c2] =
                *(const __half2*)&g_xch[(size_t)(b*SEQLEN + trl)*CONVD + DI + DS + c2];
            *(__half2*)&Bb[l*SMH + c2] = *(const __half2*)&g_prevh[poff + l*64 + c2];
        }
        __syncthreads();
        #pragma unroll
        for (int ks = 0; ks < 64; ks += 16){
            unsigned a[2][4], bf[2][2];
            #pragma unroll
            for (int i=0;i<2;i++)
                ldsm4(a[i], Ab + (wm*32 + i*16 + rowsel)*SMH + ks + koffA);
            {
                unsigned t0[4];
                ldsm4(t0, Bb + (wn*16 + nsel)*SMH + ks + koffB);
                bf[0][0]=t0[0]; bf[0][1]=t0[1]; bf[1][0]=t0[2]; bf[1][1]=t0[3];
            }
            #pragma unroll
            for (int i=0;i<2;i++)
                #pragma unroll
                for (int j=0;j<2;j++) MMA_F16(acc[i][j], a[i], bf[j]);
        }
        // scale Y_off rows by exp(acl[l]) in registers (fp32 — exact form)
        #pragma unroll
        for (int i=0;i<2;i++){
            int l0 = wm*32 + i*16 + gid;
            float e0 = eacl[l0], e1 = eacl[l0+8];
            #pragma unroll
            for (int j=0;j<2;j++){
                acc[i][j][0] *= e0; acc[i][j][1] *= e0;
                acc[i][j][2] *= e1; acc[i][j][3] *= e1;
            }
        }
        __syncthreads();
    }

    // ---- Y_diag over s-tiles <= lt (st==0 reuses the C tile already in Ab)
    for (int st = 0; st <= lt; st++){
        if (tid < 64){
            acs[tid] = ac[st*64 + tid];
            dts[tid] = g_dt[(size_t)(bb*SEQLEN + c*CHUNK_T + st*64 + tid)*NH + h];
        }
        if (st == 0 && lt == 0){
            // C already in Ab; load only Bm (which equals rows of this chunk's start)
            for (int i2 = tid; i2 < 2048; i2 += 256){
                int r = i2 >> 5, c2 = (i2 & 31) * 2;
                int tgs = c*CHUNK_T + r;
                int trs = rev ? (SEQLEN-1 - tgs) : tgs;
                *(__half2*)&Bb[r*SMH + c2] =
                    *(const __half2*)&g_xch[(size_t)(b*SEQLEN + trs)*CONVD + DI + c2];
            }
        } else if (st == 0){
            for (int i2 = tid; i2 < 2048; i2 += 256){
                int r = i2 >> 5, c2 = (i2 & 31) * 2;
                int tgs = c*CHUNK_T + r;
                int trs = rev ? (SEQLEN-1 - tgs) : tgs;
                *(__half2*)&Bb[r*SMH + c2] =
                    *(const __half2*)&g_xch[(size_t)(b*SEQLEN + trs)*CONVD + DI + c2];
            }
        } else {
            for (int i2 = tid; i2 < 2048; i2 += 256){
                int r = i2 >> 5, c2 = (i2 & 31) * 2;
                int tgl = c*CHUNK_T + lt*64 + r;
                int trl = rev ? (SEQLEN-1 - tgl) : tgl;
                *(__half2*)&Ab[r*SMH + c2] =
                    *(const __half2*)&g_xch[(size_t)(b*SEQLEN + trl)*CONVD + DI + DS + c2];
                int tgs = c*CHUNK_T + st*64 + r;
                int trs = rev ? (SEQLEN-1 - tgs) : tgs;
                *(__half2*)&Bb[r*SMH + c2] =
                    *(const __half2*)&g_xch[(size_t)(b*SEQLEN + trs)*CONVD + DI + c2];
            }
        }
        __syncthreads();
        float g[2][2][4];
        #pragma unroll
        for (int i=0;i<2;i++)
            #pragma unroll
            for (int j=0;j<2;j++)
                #pragma unroll
                for (int r=0;r<4;r++) g[i][j][r]=0.f;
        #pragma unroll
        for (int ks = 0; ks < 64; ks += 16){
            unsigned a[2][4], bf[2][2];
            #pragma unroll
            for (int i=0;i<2;i++)
                ldsm4(a[i], Ab + (wm*32 + i*16 + rowsel)*SMH + ks + koffA);
            {
                unsigned t0[4];
                ldsm4(t0, Bb + (wn*16 + nsel)*SMH + ks + koffB);
                bf[0][0]=t0[0]; bf[0][1]=t0[1]; bf[1][0]=t0[2]; bf[1][1]=t0[3];
            }
            #pragma unroll
            for (int i=0;i<2;i++)
                #pragma unroll
                for (int j=0;j<2;j++) MMA_F16(g[i][j], a[i], bf[j]);
        }
        __syncthreads();
        bool diag = (st == lt);
        #pragma unroll
        for (int i=0;i<2;i++){
            int l0 = wm*32 + i*16 + gid;
            #pragma unroll
            for (int j=0;j<2;j++){
                int s0 = wn*16 + j*8 + 2*qid;
                float al0 = acl[l0], al1 = acl[l0+8];
                float w00 = (diag && s0   > l0) ? 0.f : expf(al0 - acs[s0]);
                float w01 = (diag && s0+1 > l0) ? 0.f : expf(al0 - acs[s0+1]);
                float w10 = (diag && s0   > l0+8) ? 0.f : expf(al1 - acs[s0]);
                float w11 = (diag && s0+1 > l0+8) ? 0.f : expf(al1 - acs[s0+1]);
                Ab[l0*SMH + s0]       = __float2half(g[i][j][0]*w00);
                Ab[l0*SMH + s0+1]     = __float2half(g[i][j][1]*w01);
                Ab[(l0+8)*SMH + s0]   = __float2half(g[i][j][2]*w10);
                Ab[(l0+8)*SMH + s0+1] = __float2half(g[i][j][3]*w11);
            }
        }
        for (int idx = tid; idx < 64*64; idx += 256){
            int s = idx >> 6, p = idx & 63;
            int tgs = c*CHUNK_T + st*64 + s;
            int trs = rev ? (SEQLEN-1 - tgs) : tgs;
            float xv = __half2float(g_xch[(size_t)(b*SEQLEN + trs)*CONVD + h*HD + p]);
            Bb[p*SMH + s] = __float2half(xv * dts[s]);
        }
        __syncthreads();
        #pragma unroll
        for (int ks = 0; ks < 64; ks += 16){
            unsigned a[2][4], bf[2][2];
            #pragma unroll
            for (int i=0;i<2;i++)
                ldsm4(a[i], Ab + (wm*32 + i*16 + rowsel)*SMH + ks + koffA);
            {
                unsigned t0[4];
                ldsm4(t0, Bb + (wn*16 + nsel)*SMH + ks + koffB);
                bf[0][0]=t0[0]; bf[0][1]=t0[1]; bf[1][0]=t0[2]; bf[1][1]=t0[3];
            }
            #pragma unroll
            for (int i=0;i<2;i++)
                #pragma unroll
                for (int j=0;j<2;j++) MMA_F16(acc[i][j], a[i], bf[j]);
        }
        __syncthreads();
    }

    #pragma unroll
    for (int i=0;i<2;i++){
        int l = wm*32 + i*16 + gid;
        int tg0 = c*CHUNK_T + lt*64 + l;
        #pragma unroll
        for (int j=0;j<2;j++){
            int pc = h*HD + wn*16 + j*8 + 2*qid;
            size_t o0 = (size_t)(bb*SEQLEN + tg0)*DI + pc;
            size_t o1 = (size_t)(bb*SEQLEN + tg0 + 8)*DI + pc;
            *(__half2*)&g_yssdh[o0] = __floats2half2_rn(acc[i][j][0], acc[i][j][1]);
            *(__half2*)&g_yssdh[o1] = __floats2half2_rn(acc[i][j][2], acc[i][j][3]);
        }
    }
}

// ---------------- 10) combine + gate + RMSNorm (half2 vectorized) ----------
__global__ void combine_kernel(const float* __restrict__ Dv,
                               const float* __restrict__ rms_w){
    __shared__ float ybuf[DI];
    __shared__ float red[8];
    int bl = blockIdx.x;
    int b = bl / SEQLEN, t = bl % SEQLEN;
    int tid = threadIdx.x;
    float ss = 0.f;
    for (int d = tid*2; d < DI; d += 512){
        float2 yf = make_float2(0.f, 0.f), yb = make_float2(0.f, 0.f);
        if (t > 0)
            yf = __half22float2(*(const __half2*)&g_yssdh[(size_t)(b*SEQLEN + t - 1)*DI + d]);
        if (t <= SEQLEN-2)
            yb = __half22float2(*(const __half2*)&g_yssdh[(size_t)((2+b)*SEQLEN + (SEQLEN-2 - t))*DI + d]);
        float2 xo = __half22float2(*(const __half2*)&g_xch[(size_t)bl*CONVD + d]);
        float2 z  = __half22float2(*(const __half2*)&g_zxh[(size_t)bl*DIP + d]);
        int h = d >> 6;
        float dterm = g_dterm[(size_t)bl*NH + h] + Dv[h];
        float y0 = (yf.x + yb.x + xo.x*dterm) * siluf(z.x);
        float y1 = (yf.y + yb.y + xo.y*dterm) * siluf(z.y);
        ybuf[d] = y0; ybuf[d+1] = y1;
        ss += y0*y0 + y1*y1;
    }
    float tot = blockReduce256(ss, red);
    float inv = rsqrtf(tot/DI + EPSV);
    __syncthreads();
    for (int d = tid*2; d < DI; d += 512){
        float2 rw = *(const float2*)&rms_w[d];
        *(__half2*)&g_ynh[(size_t)bl*DI + d] =
            __floats2half2_rn(ybuf[d]*inv*rw.x, ybuf[d+1]*inv*rw.y);
    }
}

// ---------------- launch ----------------
extern "C" void kernel_launch(void* const* d_in, const int* in_sizes, int n_in,
                              void* d_out, int out_size){
    const float* x          = (const float*)d_in[0];
    const float* ln_w       = (const float*)d_in[1];
    const float* ln_b       = (const float*)d_in[2];
    const float* in_proj_w  = (const float*)d_in[3];
    const float* conv_w     = (const float*)d_in[4];
    const float* conv_b     = (const float*)d_in[5];
    const float* dt_bias    = (const float*)d_in[6];
    const float* A_log      = (const float*)d_in[7];
    const float* Dv         = (const float*)d_in[8];
    const float* fc_D_w     = (const float*)d_in[9];
    const float* rms_w      = (const float*)d_in[10];
    const float* out_proj_w = (const float*)d_in[11];
    float* out = (float*)d_out;

    __half *uh, *ynh, *wah, *woh, *zxh;
    cudaGetSymbolAddress((void**)&uh,  g_uh);
    cudaGetSymbolAddress((void**)&ynh, g_ynh);
    cudaGetSymbolAddress((void**)&wah, g_wah);
    cudaGetSymbolAddress((void**)&woh, g_woh);
    cudaGetSymbolAddress((void**)&zxh, g_zxh);

    static bool attr_set = false;
    const int gsmem   = GSTH*2*128*SMSH*(int)sizeof(__half);       // 81920 B
    const int gsmem64 = GSTH*(128+64)*SMSH*(int)sizeof(__half);    // 61440 B
    if (!attr_set){
        cudaFuncSetAttribute(gemm_h, cudaFuncAttributeMaxDynamicSharedMemorySize, gsmem);
        cudaFuncSetAttribute(gemm_h_n64, cudaFuncAttributeMaxDynamicSharedMemorySize, gsmem64);
        attr_set = true;
    }

    // fused weight-convert + LayerNorm
    prep_kernel<<<WCONV_BLKS + BL, 256>>>(in_proj_w, out_proj_w, x, ln_w, ln_b);

    // in_proj -> fp16 zx
    gemm_h<<<dim3((DIP+127)/128, BL/128), 256, gsmem>>>(uh, DM, wah, DM,
        nullptr, nullptr, zxh, DIP, BL, DIP, DM);

    conv_kernel<<<dim3(CONVD/128, SEQLEN/CTS, BATCH), 256>>>(conv_w, conv_b);
    cumsum_kernel<<<NBB*NH*NC, 256>>>(A_log, dt_bias);

    // fused chunk-states + fc_D
    states_fcd_kernel<<<NSTATES + BL/64, 256>>>(fc_D_w);

    prevscan_kernel<<<NBB*NH*4, 256>>>();
    ydiag_kernel<<<NBB*NC*NH*4, 256>>>();
    combine_kernel<<<BL, 256>>>(Dv, rms_w);

    // out_proj + residual -> fp32 out
    gemm_h_n64<<<dim3(DM/64, BL/128), 256, gsmem64>>>(ynh, DI, woh, DI,
        x, out, DM, BL, DM, DI);
}

// round 15
// speedup vs baseline: 1.1194x; 1.1194x over previous
#include <cuda_runtime.h>
#include <cuda_fp16.h>
#include <math.h>
#include <stdint.h>

// ---------------- constants ----------------
#define BATCH   2
#define SEQLEN  4096
#define BL      (BATCH*SEQLEN)          // 8192 rows
#define DM      768
#define DI      1536
#define NH      24
#define HD      64
#define DS      64
#define DCONV   7
#define CONVD   (DI + 2*DS)             // 1664
#define DIP     (2*DI + 2*DS + 2*NH)    // 3248
#define CHUNK_T 256
#define NC      (SEQLEN/CHUNK_T)        // 16
#define NBB     (2*BATCH)               // 4 direction-batches
#define EPSV    1e-5f

// ---------------- scratch ----------------
__device__ __half g_zxh[(size_t)BL*DIP];
__device__ __half g_xch[(size_t)BL*CONVD];
__device__ float g_dt[(size_t)NBB*SEQLEN*NH];
__device__ float g_acum[(size_t)NBB*NH*NC*CHUNK_T];
__device__ float g_csum[(size_t)NBB*NH*NC];
__device__ float g_states[(size_t)NBB*NC*NH*HD*DS];
__device__ __half g_prevh[(size_t)NBB*NC*NH*HD*DS];
__device__ __half g_yssdh[(size_t)NBB*SEQLEN*DI];
__device__ float g_dterm[(size_t)BL*NH];
__device__ __half g_uh[(size_t)BL*DM];
__device__ __half g_ynh[(size_t)BL*DI];
__device__ __half g_wah[(size_t)DIP*DM];
__device__ __half g_woh[(size_t)DM*DI];

// ---------------- helpers ----------------
__device__ __forceinline__ float softplusf(float x){
    return (x > 20.f) ? x : log1pf(expf(x));
}
__device__ __forceinline__ float siluf(float x){
    return x / (1.f + expf(-x));
}
#define MMA_F16(acc, a, b) \
    asm volatile("mma.sync.aligned.m16n8k16.row.col.f32.f16.f16.f32 " \
        "{%0,%1,%2,%3},{%4,%5,%6,%7},{%8,%9},{%0,%1,%2,%3};" \
        : "+f"(acc[0]),"+f"(acc[1]),"+f"(acc[2]),"+f"(acc[3]) \
        : "r"(a[0]),"r"(a[1]),"r"(a[2]),"r"(a[3]),"r"(b[0]),"r"(b[1]))

__device__ __forceinline__ void ldsm4(unsigned* r, const __half* p){
    unsigned a = (unsigned)__cvta_generic_to_shared(p);
    asm volatile("ldmatrix.sync.aligned.m8n8.x4.shared.b16 {%0,%1,%2,%3}, [%4];"
        : "=r"(r[0]),"=r"(r[1]),"=r"(r[2]),"=r"(r[3]) : "r"(a));
}

__device__ __forceinline__ void cp16(void* dst, const void* src, bool p){
    unsigned d = (unsigned)__cvta_generic_to_shared(dst);
    int sz = p ? 16 : 0;
    asm volatile("cp.async.cg.shared.global [%0], [%1], 16, %2;\n"
                 :: "r"(d), "l"(src), "r"(sz));
}
__device__ __forceinline__ void cp_commit(){ asm volatile("cp.async.commit_group;\n"); }
__device__ __forceinline__ void cp_wait2(){ asm volatile("cp.async.wait_group 2;\n"); }

__device__ __forceinline__ float blockReduce256(float v, float* red){
    int tid = threadIdx.x;
    int lane = tid & 31, w = tid >> 5;
    #pragma unroll
    for (int o = 16; o > 0; o >>= 1) v += __shfl_xor_sync(0xffffffffu, v, o);
    if (lane == 0) red[w] = v;
    __syncthreads();
    float r = (lane < 8) ? red[lane] : 0.f;
    #pragma unroll
    for (int o = 4; o > 0; o >>= 1) r += __shfl_xor_sync(0xffffffffu, r, o);
    r = __shfl_sync(0xffffffffu, r, 0);
    return r;
}

// ---------------- 0) weight convert to fp16 ----------------
__global__ void wconv_kernel(const float* __restrict__ wi,
                             const float* __restrict__ wo){
    int i = blockIdx.x*256 + threadIdx.x;
    if (i < DIP*DM) g_wah[i] = __float2half(wi[i]);
    if (i < DM*DI)  g_woh[i] = __float2half(wo[i]);
}

// ---------------- 1) LayerNorm (emits fp16) ----------------
__global__ void ln_kernel(const float* __restrict__ x,
                          const float* __restrict__ w,
                          const float* __restrict__ b){
    __shared__ float red[8];
    int row = blockIdx.x;
    const float* xr = x + (size_t)row*DM;
    int tid = threadIdx.x;
    float s = 0.f;
    for (int i = tid; i < DM; i += 256) s += xr[i];
    float mu = blockReduce256(s, red) / DM;
    __syncthreads();
    float v = 0.f;
    for (int i = tid; i < DM; i += 256){ float d = xr[i]-mu; v += d*d; }
    float var = blockReduce256(v, red) / DM;
    float inv = rsqrtf(var + EPSV);
    for (int i = tid; i < DM; i += 256)
        g_uh[(size_t)row*DM + i] = __float2half((xr[i]-mu)*inv*w[i] + b[i]);
}

// ---------------- fp16 GEMM, 4-stage cp.async, m16n8k16, ldmatrix ----------
#define SMSH 40
#define GSTH 4
__global__ __launch_bounds__(256, 2)
void gemm_h(const __half* __restrict__ A, int lda,
            const __half* __restrict__ B, int ldb,
            const float* __restrict__ R,
            float* __restrict__ C, __half* __restrict__ Ch, int ldc,
            int M, int N, int K){
    extern __shared__ __half smh[];
    __half* AsB = smh;
    __half* BsB = smh + GSTH*128*SMSH;
    const int tid  = threadIdx.x;
    const int lane = tid & 31;
    const int warp = tid >> 5;
    const int wm = warp >> 2;
    const int wn = warp & 3;
    const int m0 = blockIdx.y * 128;
    const int n0 = blockIdx.x * 128;
    const int rowsel = lane & 15;
    const int koffA  = (lane >> 4) * 8;
    const int nsel   = (lane & 7) + ((lane >> 4) * 8);
    const int koffB  = ((lane >> 3) & 1) * 8;

    float acc[4][4][4];
    #pragma unroll
    for (int i=0;i<4;i++)
        #pragma unroll
        for (int j=0;j<4;j++)
            #pragma unroll
            for (int r=0;r<4;r++) acc[i][j][r]=0.f;

    const int nk = K >> 5;
    const int c0r = tid >> 2,  c0q = tid & 3;
    const int c1r = (tid+256) >> 2, c1q = tid & 3;

    const __half* ApA = A + (size_t)(m0 + c0r)*lda + c0q*8;
    const __half* ApB = A + (size_t)(m0 + c1r)*lda + c1q*8;
    const int bn0 = n0 + c0r, bn1 = n0 + c1r;
    const __half* BpA = B + (size_t)bn0*ldb + c0q*8;
    const __half* BpB = B + (size_t)bn1*ldb + c1q*8;
    const bool bokA = bn0 < N, bokB = bn1 < N;

    #pragma unroll
    for (int s = 0; s < GSTH-1; s++){
        int ko = s << 5;
        __half* as = AsB + s*(128*SMSH);
        __half* bs = BsB + s*(128*SMSH);
        cp16(as + c0r*SMSH + c0q*8, ApA + ko, true);
        cp16(as + c1r*SMSH + c1q*8, ApB + ko, true);
        cp16(bs + c0r*SMSH + c0q*8, BpA + ko, bokA);
        cp16(bs + c1r*SMSH + c1q*8, BpB + ko, bokB);
        cp_commit();
    }

    for (int kt = 0; kt < nk; kt++){
        cp_wait2();
        __syncthreads();
        int kn = kt + GSTH - 1;
        if (kn < nk){
            int ko = kn << 5;
            int stg = kn % GSTH;
            __half* as = AsB + stg*(128*SMSH);
            __half* bs = BsB + stg*(128*SMSH);
            cp16(as + c0r*SMSH + c0q*8, ApA + ko, true);
            cp16(as + c1r*SMSH + c1q*8, ApB + ko, true);
            cp16(bs + c0r*SMSH + c0q*8, BpA + ko, bokA);
            cp16(bs + c1r*SMSH + c1q*8, BpB + ko, bokB);
        }
        cp_commit();

        const __half* As = AsB + (kt % GSTH)*(128*SMSH);
        const __half* Bs = BsB + (kt % GSTH)*(128*SMSH);
        #pragma unroll
        for (int ks = 0; ks < 32; ks += 16){
            unsigned a[4][4], bfr[4][2];
            #pragma unroll
            for (int i=0;i<4;i++)
                ldsm4(a[i], As + (wm*64 + i*16 + rowsel)*SMSH + ks + koffA);
            {
                unsigned t0[4], t1[4];
                ldsm4(t0, Bs + (wn*32 + nsel)*SMSH + ks + koffB);
                ldsm4(t1, Bs + (wn*32 + 16 + nsel)*SMSH + ks + koffB);
                bfr[0][0]=t0[0]; bfr[0][1]=t0[1]; bfr[1][0]=t0[2]; bfr[1][1]=t0[3];
                bfr[2][0]=t1[0]; bfr[2][1]=t1[1]; bfr[3][0]=t1[2]; bfr[3][1]=t1[3];
            }
            #pragma unroll
            for (int i=0;i<4;i++)
                #pragma unroll
                for (int j=0;j<4;j++) MMA_F16(acc[i][j], a[i], bfr[j]);
        }
    }

    #pragma unroll
    for (int i=0;i<4;i++){
        int r0 = m0 + wm*64 + i*16 + (lane>>2);
        #pragma unroll
        for (int j=0;j<4;j++){
            int cb = n0 + wn*32 + j*8;
            if (cb < N){
                int cc = cb + 2*(lane & 3);
                size_t o0 = (size_t)r0*ldc + cc;
                size_t o1 = (size_t)(r0+8)*ldc + cc;
                if (Ch){
                    *(__half2*)&Ch[o0] = __floats2half2_rn(acc[i][j][0], acc[i][j][1]);
                    *(__half2*)&Ch[o1] = __floats2half2_rn(acc[i][j][2], acc[i][j][3]);
                } else {
                    float v0 = acc[i][j][0], v1 = acc[i][j][1];
                    float v2 = acc[i][j][2], v3 = acc[i][j][3];
                    if (R){ v0 += R[o0]; v1 += R[o0+1]; v2 += R[o1]; v3 += R[o1+1]; }
                    C[o0] = v0; C[o0+1] = v1; C[o1] = v2; C[o1+1] = v3;
                }
            }
        }
    }
}

// ---------------- fp16 GEMM, 128xM x 64xN tile (out_proj + residual) -------
__global__ __launch_bounds__(256, 2)
void gemm_h_n64(const __half* __restrict__ A, int lda,
                const __half* __restrict__ B, int ldb,
                const float* __restrict__ R,
                float* __restrict__ C, int ldc,
                int M, int N, int K){
    extern __shared__ __half smh[];
    __half* AsB = smh;
    __half* BsB = smh + GSTH*128*SMSH;
    const int tid  = threadIdx.x;
    const int lane = tid & 31;
    const int warp = tid >> 5;
    const int wm = warp >> 2;
    const int wn = warp & 3;
    const int m0 = blockIdx.y * 128;
    const int n0 = blockIdx.x * 64;
    const int rowsel = lane & 15;
    const int koffA  = (lane >> 4) * 8;
    const int nsel   = (lane & 7) + ((lane >> 4) * 8);
    const int koffB  = ((lane >> 3) & 1) * 8;

    float acc[4][2][4];
    #pragma unroll
    for (int i=0;i<4;i++)
        #pragma unroll
        for (int j=0;j<2;j++)
            #pragma unroll
            for (int r=0;r<4;r++) acc[i][j][r]=0.f;

    const int nk = K >> 5;
    const int c0r = tid >> 2,  c0q = tid & 3;
    const int c1r = (tid+256) >> 2, c1q = tid & 3;

    const __half* ApA = A + (size_t)(m0 + c0r)*lda + c0q*8;
    const __half* ApB = A + (size_t)(m0 + c1r)*lda + c1q*8;
    const __half* Bp  = B + (size_t)(n0 + c0r)*ldb + c0q*8;
    const bool brow = c0r < 64;

    #pragma unroll
    for (int s = 0; s < GSTH-1; s++){
        int ko = s << 5;
        __half* as = AsB + s*(128*SMSH);
        __half* bs = BsB + s*(64*SMSH);
        cp16(as + c0r*SMSH + c0q*8, ApA + ko, true);
        cp16(as + c1r*SMSH + c1q*8, ApB + ko, true);
        if (brow) cp16(bs + c0r*SMSH + c0q*8, Bp + ko, true);
        cp_commit();
    }

    for (int kt = 0; kt < nk; kt++){
        cp_wait2();
        __syncthreads();
        int kn = kt + GSTH - 1;
        if (kn < nk){
            int ko = kn << 5;
            int stg = kn % GSTH;
            __half* as = AsB + stg*(128*SMSH);
            __half* bs = BsB + stg*(64*SMSH);
            cp16(as + c0r*SMSH + c0q*8, ApA + ko, true);
            cp16(as + c1r*SMSH + c1q*8, ApB + ko, true);
            if (brow) cp16(bs + c0r*SMSH + c0q*8, Bp + ko, true);
        }
        cp_commit();

        const __half* As = AsB + (kt % GSTH)*(128*SMSH);
        const __half* Bs = BsB + (kt % GSTH)*(64*SMSH);
        #pragma unroll
        for (int ks = 0; ks < 32; ks += 16){
            unsigned a[4][4], bfr[2][2];
            #pragma unroll
            for (int i=0;i<4;i++)
                ldsm4(a[i], As + (wm*64 + i*16 + rowsel)*SMSH + ks + koffA);
            {
                unsigned t0[4];
                ldsm4(t0, Bs + (wn*16 + nsel)*SMSH + ks + koffB);
                bfr[0][0]=t0[0]; bfr[0][1]=t0[1]; bfr[1][0]=t0[2]; bfr[1][1]=t0[3];
            }
            #pragma unroll
            for (int i=0;i<4;i++)
                #pragma unroll
                for (int j=0;j<2;j++) MMA_F16(acc[i][j], a[i], bfr[j]);
        }
    }

    #pragma unroll
    for (int i=0;i<4;i++){
        int r0 = m0 + wm*64 + i*16 + (lane>>2);
        #pragma unroll
        for (int j=0;j<2;j++){
            int cc = n0 + wn*16 + j*8 + 2*(lane & 3);
            size_t o0 = (size_t)r0*ldc + cc;
            size_t o1 = (size_t)(r0+8)*ldc + cc;
            float v0 = acc[i][j][0], v1 = acc[i][j][1];
            float v2 = acc[i][j][2], v3 = acc[i][j][3];
            if (R){ v0 += R[o0]; v1 += R[o0+1]; v2 += R[o1]; v3 += R[o1+1]; }
            C[o0] = v0; C[o0+1] = v1; C[o1] = v2; C[o1+1] = v3;
        }
    }
}

// ---------------- 4) conv: half2 channel pairs ----------------
#define CTS 32
__global__ void conv_kernel(const float* __restrict__ cw,
                            const float* __restrict__ cb){
    __shared__ __half2 s[CTS+6][64];
    __shared__ __half2 w[7][64];
    __shared__ __half2 bias[64];
    int ch0 = blockIdx.x * 128;
    int t0  = blockIdx.y * CTS;
    int b   = blockIdx.z;
    int tid = threadIdx.x;
    for (int i = tid; i < 7*64; i += 256){
        int j = i >> 6, cp = i & 63;
        w[j][cp] = __floats2half2_rn(cw[(size_t)(ch0+cp*2)*DCONV + j],
                                     cw[(size_t)(ch0+cp*2+1)*DCONV + j]);
    }
    if (tid < 64) bias[tid] = __floats2half2_rn(cb[ch0 + tid*2], cb[ch0 + tid*2+1]);
    for (int i = tid; i < (CTS+6)*64; i += 256){
        int tt = t0 - 6 + (i >> 6);
        int cp = i & 63;
        s[i>>6][cp] = (tt >= 0)
            ? *(const __half2*)&g_zxh[(size_t)(b*SEQLEN + tt)*DIP + DI + ch0 + cp*2]
            : __floats2half2_rn(0.f, 0.f);
    }
    __syncthreads();
    #pragma unroll
    for (int k = 0; k < 8; k++){
        int o = tid + k*256;
        int tl = o >> 6, cp = o & 63;
        float2 acc = __half22float2(bias[cp]);
        #pragma unroll
        for (int j = 0; j < 7; j++){
            float2 wv = __half22float2(w[j][cp]);
            float2 sv = __half22float2(s[tl+j][cp]);
            acc.x += wv.x*sv.x; acc.y += wv.y*sv.y;
        }
        *(__half2*)&g_xch[(size_t)(b*SEQLEN + t0 + tl)*CONVD + ch0 + cp*2]
            = __floats2half2_rn(siluf(acc.x), siluf(acc.y));
    }
}

// ---------------- 5) dt softplus + per-chunk cumsum (shfl scan) ------------
__global__ void cumsum_kernel(const float* __restrict__ A_log,
                              const float* __restrict__ dt_bias){
    int bid = blockIdx.x;            // ((bb*NH)+h)*NC + c
    int c = bid % NC;
    int h = (bid / NC) % NH;
    int bb = bid / (NC*NH);
    int b = bb & 1;
    bool rev = bb >= 2;
    int tid = threadIdx.x;
    int lane = tid & 31, warp = tid >> 5;
    float a = -expf(A_log[h]);
    int t = c*CHUNK_T + tid;
    int tg = rev ? (SEQLEN-1-t) : t;
    int col = (DIP - 2*NH) + (rev ? NH + h : h);
    float raw = __half2float(g_zxh[(size_t)(b*SEQLEN + tg)*DIP + col]);
    float dtv = softplusf(raw + dt_bias[h]);
    g_dt[(size_t)(bb*SEQLEN + t)*NH + h] = dtv;
    float v = dtv * a;
    float sc = v;
    #pragma unroll
    for (int o = 1; o < 32; o <<= 1){
        float u = __shfl_up_sync(0xffffffffu, sc, o);
        if (lane >= o) sc += u;
    }
    __shared__ float wsum[8];
    if (lane == 31) wsum[warp] = sc;
    __syncthreads();
    if (warp == 0 && lane < 8){
        float ws = wsum[lane];
        #pragma unroll
        for (int o = 1; o < 8; o <<= 1){
            float u = __shfl_up_sync(0xffu, ws, o);
            if (lane >= o) ws += u;
        }
        wsum[lane] = ws;
    }
    __syncthreads();
    float base = (warp > 0) ? wsum[warp-1] : 0.f;
    float total = sc + base;
    g_acum[(size_t)bid*CHUNK_T + tid] = total;
    if (tid == CHUNK_T-1) g_csum[bid] = total;
}

// ---------------- 6) chunk states (fp16 mma + ldmatrix) ----------------
#define SMH 88
__global__ void states_kernel(){
    int bid = blockIdx.x;            // (bb*NC+c)*NH + h
    int h = bid % NH;
    int c = (bid / NH) % NC;
    int bb = bid / (NH*NC);
    int b = bb & 1;
    bool rev = bb >= 2;
    int tid = threadIdx.x;
    int lane = tid & 31, warp = tid >> 5;
    int wm = warp >> 2, wn = warp & 3;
    int gid = lane >> 2, qid = lane & 3;
    const int rowsel = lane & 15;
    const int koffA  = (lane >> 4) * 8;
    const int nsel   = (lane & 7) + ((lane >> 4) * 8);
    const int koffB  = ((lane >> 3) & 1) * 8;

    __shared__ __half Ab[64*SMH];
    __shared__ __half Bb[64*SMH];
    __shared__ float dtl[64], decl[64];

    const float* ac = g_acum + ((size_t)(bb*NH + h)*NC + c)*CHUNK_T;
    float cs = g_csum[(bb*NH + h)*NC + c];

    float acc[2][2][4];
    #pragma unroll
    for (int i=0;i<2;i++)
        #pragma unroll
        for (int j=0;j<2;j++)
            #pragma unroll
            for (int r=0;r<4;r++) acc[i][j][r]=0.f;

    for (int ltile = 0; ltile < 4; ltile++){
        if (tid < 64){
            int lc2 = ltile*64 + tid;
            int tgl = c*CHUNK_T + lc2;
            dtl[tid] = g_dt[(size_t)(bb*SEQLEN + tgl)*NH + h];
            decl[tid] = expf(cs - ac[lc2]);
        }
        __syncthreads();
        for (int idx = tid; idx < 64*64; idx += 256){
            int l = idx >> 6, q = idx & 63;
            int tgl = c*CHUNK_T + ltile*64 + l;
            int trow = rev ? (SEQLEN-1 - tgl) : tgl;
            size_t roff = (size_t)(b*SEQLEN + trow)*CONVD;
            float xv = __half2float(g_xch[roff + h*HD + q]);
            float bv = __half2float(g_xch[roff + DI + q]);
            Ab[q*SMH + l] = __float2half(xv * dtl[l]);
            Bb[q*SMH + l] = __float2half(bv * decl[l]);
        }
        __syncthreads();
        #pragma unroll
        for (int ks = 0; ks < 64; ks += 16){
            unsigned a[2][4], bf[2][2];
            #pragma unroll
            for (int i=0;i<2;i++)
                ldsm4(a[i], Ab + (wm*32 + i*16 + rowsel)*SMH + ks + koffA);
            {
                unsigned t0[4];
                ldsm4(t0, Bb + (wn*16 + nsel)*SMH + ks + koffB);
                bf[0][0]=t0[0]; bf[0][1]=t0[1]; bf[1][0]=t0[2]; bf[1][1]=t0[3];
            }
            #pragma unroll
            for (int i=0;i<2;i++)
                #pragma unroll
                for (int j=0;j<2;j++) MMA_F16(acc[i][j], a[i], bf[j]);
        }
        __syncthreads();
    }
    float* sp = g_states + (size_t)bid*(HD*DS);
    #pragma unroll
    for (int i=0;i<2;i++){
        int p = wm*32 + i*16 + gid;
        #pragma unroll
        for (int j=0;j<2;j++){
            int n = wn*16 + j*8 + 2*qid;
            sp[p*DS + n]     = acc[i][j][0];
            sp[p*DS + n + 1] = acc[i][j][1];
            sp[(p+8)*DS + n]     = acc[i][j][2];
            sp[(p+8)*DS + n + 1] = acc[i][j][3];
        }
    }
}

// ---------------- 7) inter-chunk scan (4-way split) ----------------
__global__ void prevscan_kernel(){
    int bid = blockIdx.x;
    int part = bid & 3;
    int bh = bid >> 2;
    int bb = bh / NH, h = bh % NH;
    int tid = threadIdx.x;
    int base = part*1024 + tid;
    float run[4];
    #pragma unroll
    for (int k = 0; k < 4; k++) run[k] = 0.f;
    for (int c = 0; c < NC; c++){
        size_t off = ((size_t)(bb*NC + c)*NH + h)*(HD*DS);
        float e = expf(g_csum[bh*NC + c]);
        #pragma unroll
        for (int k = 0; k < 4; k++){
            int idx = base + k*256;
            g_prevh[off + idx] = __float2half(run[k]);
            run[k] = run[k]*e + g_states[off + idx];
        }
    }
}

// ---------------- 8) Y = Y_diag + Y_off (fp16 mma + ldmatrix) --------------
__global__ void ydiag_kernel(){
    int bid = blockIdx.x;            // ((bb*NC+c)*NH+h)*4 + lt
    int lt = bid & 3;
    int h  = (bid >> 2) % NH;
    int c  = (bid / (4*NH)) % NC;
    int bb = bid / (4*NH*NC);
    int b = bb & 1;
    bool rev = bb >= 2;
    int tid = threadIdx.x;
    int lane = tid & 31, warp = tid >> 5;
    int wm = warp >> 2, wn = warp & 3;
    int gid = lane >> 2, qid = lane & 3;
    const int rowsel = lane & 15;
    const int koffA  = (lane >> 4) * 8;
    const int nsel   = (lane & 7) + ((lane >> 4) * 8);
    const int koffB  = ((lane >> 3) & 1) * 8;

    __shared__ __half Ab[64*SMH];
    __shared__ __half Bb[64*SMH];
    __shared__ float acl[64], eacl[64], acs[64], dts[64];

    const float* ac = g_acum + ((size_t)(bb*NH + h)*NC + c)*CHUNK_T;

    if (tid < 64){
        float v = ac[lt*64 + tid];
        acl[tid] = v;
        eacl[tid] = expf(v);
    }
    __syncthreads();

    float acc[2][2][4];
    #pragma unroll
    for (int i=0;i<2;i++)
        #pragma unroll
        for (int j=0;j<2;j++)
            #pragma unroll
            for (int r=0;r<4;r++) acc[i][j][r]=0.f;

    // ---- Y_off
    {
        size_t poff = ((size_t)(bb*NC + c)*NH + h)*(HD*DS);
        for (int i2 = tid; i2 < 2048; i2 += 256){
            int l = i2 >> 5, c2 = (i2 & 31) * 2;
            int tgl = c*CHUNK_T + lt*64 + l;
            int trl = rev ? (SEQLEN-1 - tgl) : tgl;
            __half2 cv = *(const __half2*)&g_xch[(size_t)(b*SEQLEN + trl)*CONVD + DI + DS + c2];
            float2 cf = __half22float2(cv);
            float e = eacl[l];
            *(__half2*)&Ab[l*SMH + c2] = __floats2half2_rn(cf.x*e, cf.y*e);
            *(__half2*)&Bb[l*SMH + c2] = *(const __half2*)&g_prevh[poff + l*64 + c2];
        }
        __syncthreads();
        #pragma unroll
        for (int ks = 0; ks < 64; ks += 16){
            unsigned a[2][4], bf[2][2];
            #pragma unroll
            for (int i=0;i<2;i++)
                ldsm4(a[i], Ab + (wm*32 + i*16 + rowsel)*SMH + ks + koffA);
            {
                unsigned t0[4];
                ldsm4(t0, Bb + (wn*16 + nsel)*SMH + ks + koffB);
                bf[0][0]=t0[0]; bf[0][1]=t0[1]; bf[1][0]=t0[2]; bf[1][1]=t0[3];
            }
            #pragma unroll
            for (int i=0;i<2;i++)
                #pragma unroll
                for (int j=0;j<2;j++) MMA_F16(acc[i][j], a[i], bf[j]);
        }
        __syncthreads();
    }

    // ---- Y_diag over s-tiles <= lt
    for (int st = 0; st <= lt; st++){
        if (tid < 64){
            acs[tid] = ac[st*64 + tid];
            dts[tid] = g_dt[(size_t)(bb*SEQLEN + c*CHUNK_T + st*64 + tid)*NH + h];
        }
        for (int i2 = tid; i2 < 2048; i2 += 256){
            int r = i2 >> 5, c2 = (i2 & 31) * 2;
            int tgl = c*CHUNK_T + lt*64 + r;
            int trl = rev ? (SEQLEN-1 - tgl) : tgl;
            *(__half2*)&Ab[r*SMH + c2] =
                *(const __half2*)&g_xch[(size_t)(b*SEQLEN + trl)*CONVD + DI + DS + c2];
            int tgs = c*CHUNK_T + st*64 + r;
            int trs = rev ? (SEQLEN-1 - tgs) : tgs;
            *(__half2*)&Bb[r*SMH + c2] =
                *(const __half2*)&g_xch[(size_t)(b*SEQLEN + trs)*CONVD + DI + c2];
        }
        __syncthreads();
        float g[2][2][4];
        #pragma unroll
        for (int i=0;i<2;i++)
            #pragma unroll
            for (int j=0;j<2;j++)
                #pragma unroll
                for (int r=0;r<4;r++) g[i][j][r]=0.f;
        #pragma unroll
        for (int ks = 0; ks < 64; ks += 16){
            unsigned a[2][4], bf[2][2];
            #pragma unroll
            for (int i=0;i<2;i++)
                ldsm4(a[i], Ab + (wm*32 + i*16 + rowsel)*SMH + ks + koffA);
            {
                unsigned t0[4];
                ldsm4(t0, Bb + (wn*16 + nsel)*SMH + ks + koffB);
                bf[0][0]=t0[0]; bf[0][1]=t0[1]; bf[1][0]=t0[2]; bf[1][1]=t0[3];
            }
            #pragma unroll
            for (int i=0;i<2;i++)
                #pragma unroll
                for (int j=0;j<2;j++) MMA_F16(g[i][j], a[i], bf[j]);
        }
        __syncthreads();
        bool diag = (st == lt);
        #pragma unroll
        for (int i=0;i<2;i++){
            int l0 = wm*32 + i*16 + gid;
            #pragma unroll
            for (int j=0;j<2;j++){
                int s0 = wn*16 + j*8 + 2*qid;
                float al0 = acl[l0], al1 = acl[l0+8];
                float w00 = (diag && s0   > l0) ? 0.f : expf(al0 - acs[s0]);
                float w01 = (diag && s0+1 > l0) ? 0.f : expf(al0 - acs[s0+1]);
                float w10 = (diag && s0   > l0+8) ? 0.f : expf(al1 - acs[s0]);
                float w11 = (diag && s0+1 > l0+8) ? 0.f : expf(al1 - acs[s0+1]);
                Ab[l0*SMH + s0]       = __float2half(g[i][j][0]*w00);
                Ab[l0*SMH + s0+1]     = __float2half(g[i][j][1]*w01);
                Ab[(l0+8)*SMH + s0]   = __float2half(g[i][j][2]*w10);
                Ab[(l0+8)*SMH + s0+1] = __float2half(g[i][j][3]*w11);
            }
        }
        for (int idx = tid; idx < 64*64; idx += 256){
            int s = idx >> 6, p = idx & 63;
            int tgs = c*CHUNK_T + st*64 + s;
            int trs = rev ? (SEQLEN-1 - tgs) : tgs;
            float xv = __half2float(g_xch[(size_t)(b*SEQLEN + trs)*CONVD + h*HD + p]);
            Bb[p*SMH + s] = __float2half(xv * dts[s]);
        }
        __syncthreads();
        #pragma unroll
        for (int ks = 0; ks < 64; ks += 16){
            unsigned a[2][4], bf[2][2];
            #pragma unroll
            for (int i=0;i<2;i++)
                ldsm4(a[i], Ab + (wm*32 + i*16 + rowsel)*SMH + ks + koffA);
            {
                unsigned t0[4];
                ldsm4(t0, Bb + (wn*16 + nsel)*SMH + ks + koffB);
                bf[0][0]=t0[0]; bf[0][1]=t0[1]; bf[1][0]=t0[2]; bf[1][1]=t0[3];
            }
            #pragma unroll
            for (int i=0;i<2;i++)
                #pragma unroll
                for (int j=0;j<2;j++) MMA_F16(acc[i][j], a[i], bf[j]);
        }
        __syncthreads();
    }

    #pragma unroll
    for (int i=0;i<2;i++){
        int l = wm*32 + i*16 + gid;
        int tg0 = c*CHUNK_T + lt*64 + l;
        #pragma unroll
        for (int j=0;j<2;j++){
            int pc = h*HD + wn*16 + j*8 + 2*qid;
            size_t o0 = (size_t)(bb*SEQLEN + tg0)*DI + pc;
            size_t o1 = (size_t)(bb*SEQLEN + tg0 + 8)*DI + pc;
            *(__half2*)&g_yssdh[o0] = __floats2half2_rn(acc[i][j][0], acc[i][j][1]);
            *(__half2*)&g_yssdh[o1] = __floats2half2_rn(acc[i][j][2], acc[i][j][3]);
        }
    }
}

// ---------------- 9) fc_D (fp16 inputs) ----------------
__global__ void fcd_kernel(const float* __restrict__ fw){
    __shared__ float ws[NH][132];
    int r0 = blockIdx.x * 64;
    int tid = threadIdx.x;
    int rl = tid >> 2;
    int lj = tid & 3;
    float acc[6] = {0.f,0.f,0.f,0.f,0.f,0.f};
    for (int k0 = 0; k0 < DI; k0 += 128){
        for (int i = tid; i < NH*128; i += 256)
            ws[i>>7][i&127] = fw[(size_t)(i>>7)*DI + k0 + (i&127)];
        __syncthreads();
        const __half2* xr = (const __half2*)&g_xch[(size_t)(r0+rl)*CONVD + k0];
        #pragma unroll 16
        for (int kk = 0; kk < 64; kk += 2){
            float2 x0 = __half22float2(xr[kk]);
            float2 x1 = __half22float2(xr[kk+1]);
            #pragma unroll
            for (int hh = 0; hh < 6; hh++){
                int h = lj*6 + hh;
                acc[hh] += x0.x*ws[h][kk*2] + x0.y*ws[h][kk*2+1]
                         + x1.x*ws[h][kk*2+2] + x1.y*ws[h][kk*2+3];
            }
        }
        __syncthreads();
    }
    #pragma unroll
    for (int hh = 0; hh < 6; hh++)
        g_dterm[(size_t)(r0+rl)*NH + lj*6 + hh] = acc[hh];
}

// ---------------- 10) combine + gate + RMSNorm (half2 vectorized) ----------
__global__ void combine_kernel(const float* __restrict__ Dv,
                               const float* __restrict__ rms_w){
    __shared__ float ybuf[DI];
    __shared__ float red[8];
    int bl = blockIdx.x;
    int b = bl / SEQLEN, t = bl % SEQLEN;
    int tid = threadIdx.x;
    float ss = 0.f;
    for (int d = tid*2; d < DI; d += 512){
        float2 yf = make_float2(0.f, 0.f), yb = make_float2(0.f, 0.f);
        if (t > 0)
            yf = __half22float2(*(const __half2*)&g_yssdh[(size_t)(b*SEQLEN + t - 1)*DI + d]);
        if (t <= SEQLEN-2)
            yb = __half22float2(*(const __half2*)&g_yssdh[(size_t)((2+b)*SEQLEN + (SEQLEN-2 - t))*DI + d]);
        float2 xo = __half22float2(*(const __half2*)&g_xch[(size_t)bl*CONVD + d]);
        float2 z  = __half22float2(*(const __half2*)&g_zxh[(size_t)bl*DIP + d]);
        int h = d >> 6;
        float dterm = g_dterm[(size_t)bl*NH + h] + Dv[h];
        float y0 = (yf.x + yb.x + xo.x*dterm) * siluf(z.x);
        float y1 = (yf.y + yb.y + xo.y*dterm) * siluf(z.y);
        ybuf[d] = y0; ybuf[d+1] = y1;
        ss += y0*y0 + y1*y1;
    }
    float tot = blockReduce256(ss, red);
    float inv = rsqrtf(tot/DI + EPSV);
    __syncthreads();
    for (int d = tid*2; d < DI; d += 512){
        float2 rw = *(const float2*)&rms_w[d];
        *(__half2*)&g_ynh[(size_t)bl*DI + d] =
            __floats2half2_rn(ybuf[d]*inv*rw.x, ybuf[d+1]*inv*rw.y);
    }
}

// ---------------- launch ----------------
extern "C" void kernel_launch(void* const* d_in, const int* in_sizes, int n_in,
                              void* d_out, int out_size){
    const float* x          = (const float*)d_in[0];
    const float* ln_w       = (const float*)d_in[1];
    const float* ln_b       = (const float*)d_in[2];
    const float* in_proj_w  = (const float*)d_in[3];
    const float* conv_w     = (const float*)d_in[4];
    const float* conv_b     = (const float*)d_in[5];
    const float* dt_bias    = (const float*)d_in[6];
    const float* A_log      = (const float*)d_in[7];
    const float* Dv         = (const float*)d_in[8];
    const float* fc_D_w     = (const float*)d_in[9];
    const float* rms_w      = (const float*)d_in[10];
    const float* out_proj_w = (const float*)d_in[11];
    float* out = (float*)d_out;

    __half *uh, *ynh, *wah, *woh, *zxh;
    cudaGetSymbolAddress((void**)&uh,  g_uh);
    cudaGetSymbolAddress((void**)&ynh, g_ynh);
    cudaGetSymbolAddress((void**)&wah, g_wah);
    cudaGetSymbolAddress((void**)&woh, g_woh);
    cudaGetSymbolAddress((void**)&zxh, g_zxh);

    static bool attr_set = false;
    const int gsmem   = GSTH*2*128*SMSH*(int)sizeof(__half);       // 81920 B
    const int gsmem64 = GSTH*(128+64)*SMSH*(int)sizeof(__half);    // 61440 B
    if (!attr_set){
        cudaFuncSetAttribute(gemm_h, cudaFuncAttributeMaxDynamicSharedMemorySize, gsmem);
        cudaFuncSetAttribute(gemm_h_n64, cudaFuncAttributeMaxDynamicSharedMemorySize, gsmem64);
        attr_set = true;
    }

    wconv_kernel<<<(DIP*DM + 255)/256, 256>>>(in_proj_w, out_proj_w);
    ln_kernel<<<BL, 256>>>(x, ln_w, ln_b);

    // in_proj -> fp16 zx  (128x128 tiles, GSTH=4 — best known)
    gemm_h<<<dim3((DIP+127)/128, BL/128), 256, gsmem>>>(uh, DM, wah, DM,
        nullptr, nullptr, zxh, DIP, BL, DIP, DM);

    conv_kernel<<<dim3(CONVD/128, SEQLEN/CTS, BATCH), 256>>>(conv_w, conv_b);
    cumsum_kernel<<<NBB*NH*NC, 256>>>(A_log, dt_bias);
    states_kernel<<<NBB*NC*NH, 256>>>();
    prevscan_kernel<<<NBB*NH*4, 256>>>();
    ydiag_kernel<<<NBB*NC*NH*4, 256>>>();
    fcd_kernel<<<BL/64, 256>>>(fc_D_w);
    combine_kernel<<<BL, 256>>>(Dv, rms_w);

    // out_proj + residual -> fp32 out
    gemm_h_n64<<<dim3(DM/64, BL/128), 256, gsmem64>>>(ynh, DI, woh, DI,
        x, out, DM, BL, DM, DI);
}

// round 16
// speedup vs baseline: 1.1682x; 1.0436x over previous
#include <cuda_runtime.h>
#include <cuda_fp16.h>
#include <math.h>
#include <stdint.h>

// ---------------- constants ----------------
#define BATCH   2
#define SEQLEN  4096
#define BL      (BATCH*SEQLEN)          // 8192 rows
#define DM      768
#define DI      1536
#define NH      24
#define HD      64
#define DS      64
#define DCONV   7
#define CONVD   (DI + 2*DS)             // 1664
#define DIP     (2*DI + 2*DS + 2*NH)    // 3248
#define CHUNK_T 256
#define NC      (SEQLEN/CHUNK_T)        // 16
#define NBB     (2*BATCH)               // 4 direction-batches
#define EPSV    1e-5f

// ---------------- scratch ----------------
__device__ __half g_zxh[(size_t)BL*DIP];
__device__ __half g_xch[(size_t)BL*CONVD];
__device__ float g_dt[(size_t)NBB*SEQLEN*NH];
__device__ float g_acum[(size_t)NBB*NH*NC*CHUNK_T];
__device__ float g_csum[(size_t)NBB*NH*NC];
__device__ float g_states[(size_t)NBB*NC*NH*HD*DS];
__device__ __half g_prevh[(size_t)NBB*NC*NH*HD*DS];
__device__ __half g_yssdh[(size_t)NBB*SEQLEN*DI];
__device__ float g_dterm[(size_t)BL*NH];
__device__ __half g_uh[(size_t)BL*DM];
__device__ __half g_ynh[(size_t)BL*DI];
__device__ __half g_wah[(size_t)DIP*DM];
__device__ __half g_woh[(size_t)DM*DI];

// ---------------- helpers ----------------
__device__ __forceinline__ float softplusf(float x){
    return (x > 20.f) ? x : log1pf(expf(x));
}
__device__ __forceinline__ float siluf(float x){
    return x / (1.f + expf(-x));
}
#define MMA_F16(acc, a, b) \
    asm volatile("mma.sync.aligned.m16n8k16.row.col.f32.f16.f16.f32 " \
        "{%0,%1,%2,%3},{%4,%5,%6,%7},{%8,%9},{%0,%1,%2,%3};" \
        : "+f"(acc[0]),"+f"(acc[1]),"+f"(acc[2]),"+f"(acc[3]) \
        : "r"(a[0]),"r"(a[1]),"r"(a[2]),"r"(a[3]),"r"(b[0]),"r"(b[1]))

__device__ __forceinline__ void ldsm4(unsigned* r, const __half* p){
    unsigned a = (unsigned)__cvta_generic_to_shared(p);
    asm volatile("ldmatrix.sync.aligned.m8n8.x4.shared.b16 {%0,%1,%2,%3}, [%4];"
        : "=r"(r[0]),"=r"(r[1]),"=r"(r[2]),"=r"(r[3]) : "r"(a));
}

__device__ __forceinline__ void cp16(void* dst, const void* src, bool p){
    unsigned d = (unsigned)__cvta_generic_to_shared(dst);
    int sz = p ? 16 : 0;
    asm volatile("cp.async.cg.shared.global [%0], [%1], 16, %2;\n"
                 :: "r"(d), "l"(src), "r"(sz));
}
__device__ __forceinline__ void cp_commit(){ asm volatile("cp.async.commit_group;\n"); }
__device__ __forceinline__ void cp_wait2(){ asm volatile("cp.async.wait_group 2;\n"); }

__device__ __forceinline__ float blockReduce256(float v, float* red){
    int tid = threadIdx.x;
    int lane = tid & 31, w = tid >> 5;
    #pragma unroll
    for (int o = 16; o > 0; o >>= 1) v += __shfl_xor_sync(0xffffffffu, v, o);
    if (lane == 0) red[w] = v;
    __syncthreads();
    float r = (lane < 8) ? red[lane] : 0.f;
    #pragma unroll
    for (int o = 4; o > 0; o >>= 1) r += __shfl_xor_sync(0xffffffffu, r, o);
    r = __shfl_sync(0xffffffffu, r, 0);
    return r;
}

// ---------------- 0) weight convert to fp16 ----------------
__global__ void wconv_kernel(const float* __restrict__ wi,
                             const float* __restrict__ wo){
    int i = blockIdx.x*256 + threadIdx.x;
    if (i < DIP*DM) g_wah[i] = __float2half(wi[i]);
    if (i < DM*DI)  g_woh[i] = __float2half(wo[i]);
}

// ---------------- 1) LayerNorm (emits fp16) ----------------
__global__ void ln_kernel(const float* __restrict__ x,
                          const float* __restrict__ w,
                          const float* __restrict__ b){
    __shared__ float red[8];
    int row = blockIdx.x;
    const float* xr = x + (size_t)row*DM;
    int tid = threadIdx.x;
    float s = 0.f;
    for (int i = tid; i < DM; i += 256) s += xr[i];
    float mu = blockReduce256(s, red) / DM;
    __syncthreads();
    float v = 0.f;
    for (int i = tid; i < DM; i += 256){ float d = xr[i]-mu; v += d*d; }
    float var = blockReduce256(v, red) / DM;
    float inv = rsqrtf(var + EPSV);
    for (int i = tid; i < DM; i += 256)
        g_uh[(size_t)row*DM + i] = __float2half((xr[i]-mu)*inv*w[i] + b[i]);
}

// ---------------- fp16 GEMM, 4-stage cp.async, m16n8k16, ldmatrix ----------
#define SMSH 40
#define GSTH 4
__global__ __launch_bounds__(256, 2)
void gemm_h(const __half* __restrict__ A, int lda,
            const __half* __restrict__ B, int ldb,
            const float* __restrict__ R,
            float* __restrict__ C, __half* __restrict__ Ch, int ldc,
            int M, int N, int K){
    extern __shared__ __half smh[];
    __half* AsB = smh;
    __half* BsB = smh + GSTH*128*SMSH;
    const int tid  = threadIdx.x;
    const int lane = tid & 31;
    const int warp = tid >> 5;
    const int wm = warp >> 2;
    const int wn = warp & 3;
    const int m0 = blockIdx.y * 128;
    const int n0 = blockIdx.x * 128;
    const int rowsel = lane & 15;
    const int koffA  = (lane >> 4) * 8;
    const int nsel   = (lane & 7) + ((lane >> 4) * 8);
    const int koffB  = ((lane >> 3) & 1) * 8;

    float acc[4][4][4];
    #pragma unroll
    for (int i=0;i<4;i++)
        #pragma unroll
        for (int j=0;j<4;j++)
            #pragma unroll
            for (int r=0;r<4;r++) acc[i][j][r]=0.f;

    const int nk = K >> 5;
    const int c0r = tid >> 2,  c0q = tid & 3;
    const int c1r = (tid+256) >> 2, c1q = tid & 3;

    const __half* ApA = A + (size_t)(m0 + c0r)*lda + c0q*8;
    const __half* ApB = A + (size_t)(m0 + c1r)*lda + c1q*8;
    const int bn0 = n0 + c0r, bn1 = n0 + c1r;
    const __half* BpA = B + (size_t)bn0*ldb + c0q*8;
    const __half* BpB = B + (size_t)bn1*ldb + c1q*8;
    const bool bokA = bn0 < N, bokB = bn1 < N;

    #pragma unroll
    for (int s = 0; s < GSTH-1; s++){
        int ko = s << 5;
        __half* as = AsB + s*(128*SMSH);
        __half* bs = BsB + s*(128*SMSH);
        cp16(as + c0r*SMSH + c0q*8, ApA + ko, true);
        cp16(as + c1r*SMSH + c1q*8, ApB + ko, true);
        cp16(bs + c0r*SMSH + c0q*8, BpA + ko, bokA);
        cp16(bs + c1r*SMSH + c1q*8, BpB + ko, bokB);
        cp_commit();
    }

    for (int kt = 0; kt < nk; kt++){
        cp_wait2();
        __syncthreads();
        int kn = kt + GSTH - 1;
        if (kn < nk){
            int ko = kn << 5;
            int stg = kn % GSTH;
            __half* as = AsB + stg*(128*SMSH);
            __half* bs = BsB + stg*(128*SMSH);
            cp16(as + c0r*SMSH + c0q*8, ApA + ko, true);
            cp16(as + c1r*SMSH + c1q*8, ApB + ko, true);
            cp16(bs + c0r*SMSH + c0q*8, BpA + ko, bokA);
            cp16(bs + c1r*SMSH + c1q*8, BpB + ko, bokB);
        }
        cp_commit();

        const __half* As = AsB + (kt % GSTH)*(128*SMSH);
        const __half* Bs = BsB + (kt % GSTH)*(128*SMSH);
        #pragma unroll
        for (int ks = 0; ks < 32; ks += 16){
            unsigned a[4][4], bfr[4][2];
            #pragma unroll
            for (int i=0;i<4;i++)
                ldsm4(a[i], As + (wm*64 + i*16 + rowsel)*SMSH + ks + koffA);
            {
                unsigned t0[4], t1[4];
                ldsm4(t0, Bs + (wn*32 + nsel)*SMSH + ks + koffB);
                ldsm4(t1, Bs + (wn*32 + 16 + nsel)*SMSH + ks + koffB);
                bfr[0][0]=t0[0]; bfr[0][1]=t0[1]; bfr[1][0]=t0[2]; bfr[1][1]=t0[3];
                bfr[2][0]=t1[0]; bfr[2][1]=t1[1]; bfr[3][0]=t1[2]; bfr[3][1]=t1[3];
            }
            #pragma unroll
            for (int i=0;i<4;i++)
                #pragma unroll
                for (int j=0;j<4;j++) MMA_F16(acc[i][j], a[i], bfr[j]);
        }
    }

    #pragma unroll
    for (int i=0;i<4;i++){
        int r0 = m0 + wm*64 + i*16 + (lane>>2);
        #pragma unroll
        for (int j=0;j<4;j++){
            int cb = n0 + wn*32 + j*8;
            if (cb < N){
                int cc = cb + 2*(lane & 3);
                size_t o0 = (size_t)r0*ldc + cc;
                size_t o1 = (size_t)(r0+8)*ldc + cc;
                if (Ch){
                    *(__half2*)&Ch[o0] = __floats2half2_rn(acc[i][j][0], acc[i][j][1]);
                    *(__half2*)&Ch[o1] = __floats2half2_rn(acc[i][j][2], acc[i][j][3]);
                } else {
                    float v0 = acc[i][j][0], v1 = acc[i][j][1];
                    float v2 = acc[i][j][2], v3 = acc[i][j][3];
                    if (R){ v0 += R[o0]; v1 += R[o0+1]; v2 += R[o1]; v3 += R[o1+1]; }
                    C[o0] = v0; C[o0+1] = v1; C[o1] = v2; C[o1+1] = v3;
                }
            }
        }
    }
}

// ---------------- fp16 GEMM, 128xM x 64xN tile (out_proj + residual) -------
__global__ __launch_bounds__(256, 2)
void gemm_h_n64(const __half* __restrict__ A, int lda,
                const __half* __restrict__ B, int ldb,
                const float* __restrict__ R,
                float* __restrict__ C, int ldc,
                int M, int N, int K){
    extern __shared__ __half smh[];
    __half* AsB = smh;
    __half* BsB = smh + GSTH*128*SMSH;
    const int tid  = threadIdx.x;
    const int lane = tid & 31;
    const int warp = tid >> 5;
    const int wm = warp >> 2;
    const int wn = warp & 3;
    const int m0 = blockIdx.y * 128;
    const int n0 = blockIdx.x * 64;
    const int rowsel = lane & 15;
    const int koffA  = (lane >> 4) * 8;
    const int nsel   = (lane & 7) + ((lane >> 4) * 8);
    const int koffB  = ((lane >> 3) & 1) * 8;

    float acc[4][2][4];
    #pragma unroll
    for (int i=0;i<4;i++)
        #pragma unroll
        for (int j=0;j<2;j++)
            #pragma unroll
            for (int r=0;r<4;r++) acc[i][j][r]=0.f;

    const int nk = K >> 5;
    const int c0r = tid >> 2,  c0q = tid & 3;
    const int c1r = (tid+256) >> 2, c1q = tid & 3;

    const __half* ApA = A + (size_t)(m0 + c0r)*lda + c0q*8;
    const __half* ApB = A + (size_t)(m0 + c1r)*lda + c1q*8;
    const __half* Bp  = B + (size_t)(n0 + c0r)*ldb + c0q*8;
    const bool brow = c0r < 64;

    #pragma unroll
    for (int s = 0; s < GSTH-1; s++){
        int ko = s << 5;
        __half* as = AsB + s*(128*SMSH);
        __half* bs = BsB + s*(64*SMSH);
        cp16(as + c0r*SMSH + c0q*8, ApA + ko, true);
        cp16(as + c1r*SMSH + c1q*8, ApB + ko, true);
        if (brow) cp16(bs + c0r*SMSH + c0q*8, Bp + ko, true);
        cp_commit();
    }

    for (int kt = 0; kt < nk; kt++){
        cp_wait2();
        __syncthreads();
        int kn = kt + GSTH - 1;
        if (kn < nk){
            int ko = kn << 5;
            int stg = kn % GSTH;
            __half* as = AsB + stg*(128*SMSH);
            __half* bs = BsB + stg*(64*SMSH);
            cp16(as + c0r*SMSH + c0q*8, ApA + ko, true);
            cp16(as + c1r*SMSH + c1q*8, ApB + ko, true);
            if (brow) cp16(bs + c0r*SMSH + c0q*8, Bp + ko, true);
        }
        cp_commit();

        const __half* As = AsB + (kt % GSTH)*(128*SMSH);
        const __half* Bs = BsB + (kt % GSTH)*(64*SMSH);
        #pragma unroll
        for (int ks = 0; ks < 32; ks += 16){
            unsigned a[4][4], bfr[2][2];
            #pragma unroll
            for (int i=0;i<4;i++)
                ldsm4(a[i], As + (wm*64 + i*16 + rowsel)*SMSH + ks + koffA);
            {
                unsigned t0[4];
                ldsm4(t0, Bs + (wn*16 + nsel)*SMSH + ks + koffB);
                bfr[0][0]=t0[0]; bfr[0][1]=t0[1]; bfr[1][0]=t0[2]; bfr[1][1]=t0[3];
            }
            #pragma unroll
            for (int i=0;i<4;i++)
                #pragma unroll
                for (int j=0;j<2;j++) MMA_F16(acc[i][j], a[i], bfr[j]);
        }
    }

    #pragma unroll
    for (int i=0;i<4;i++){
        int r0 = m0 + wm*64 + i*16 + (lane>>2);
        #pragma unroll
        for (int j=0;j<2;j++){
            int cc = n0 + wn*16 + j*8 + 2*(lane & 3);
            size_t o0 = (size_t)r0*ldc + cc;
            size_t o1 = (size_t)(r0+8)*ldc + cc;
            float v0 = acc[i][j][0], v1 = acc[i][j][1];
            float v2 = acc[i][j][2], v3 = acc[i][j][3];
            if (R){ v0 += R[o0]; v1 += R[o0+1]; v2 += R[o1]; v3 += R[o1+1]; }
            C[o0] = v0; C[o0+1] = v1; C[o1] = v2; C[o1+1] = v3;
        }
    }
}

// ---------------- 4) conv: half2 channel pairs ----------------
#define CTS 32
__global__ void conv_kernel(const float* __restrict__ cw,
                            const float* __restrict__ cb){
    __shared__ __half2 s[CTS+6][64];
    __shared__ __half2 w[7][64];
    __shared__ __half2 bias[64];
    int ch0 = blockIdx.x * 128;
    int t0  = blockIdx.y * CTS;
    int b   = blockIdx.z;
    int tid = threadIdx.x;
    for (int i = tid; i < 7*64; i += 256){
        int j = i >> 6, cp = i & 63;
        w[j][cp] = __floats2half2_rn(cw[(size_t)(ch0+cp*2)*DCONV + j],
                                     cw[(size_t)(ch0+cp*2+1)*DCONV + j]);
    }
    if (tid < 64) bias[tid] = __floats2half2_rn(cb[ch0 + tid*2], cb[ch0 + tid*2+1]);
    for (int i = tid; i < (CTS+6)*64; i += 256){
        int tt = t0 - 6 + (i >> 6);
        int cp = i & 63;
        s[i>>6][cp] = (tt >= 0)
            ? *(const __half2*)&g_zxh[(size_t)(b*SEQLEN + tt)*DIP + DI + ch0 + cp*2]
            : __floats2half2_rn(0.f, 0.f);
    }
    __syncthreads();
    #pragma unroll
    for (int k = 0; k < 8; k++){
        int o = tid + k*256;
        int tl = o >> 6, cp = o & 63;
        float2 acc = __half22float2(bias[cp]);
        #pragma unroll
        for (int j = 0; j < 7; j++){
            float2 wv = __half22float2(w[j][cp]);
            float2 sv = __half22float2(s[tl+j][cp]);
            acc.x += wv.x*sv.x; acc.y += wv.y*sv.y;
        }
        *(__half2*)&g_xch[(size_t)(b*SEQLEN + t0 + tl)*CONVD + ch0 + cp*2]
            = __floats2half2_rn(siluf(acc.x), siluf(acc.y));
    }
}

// ---------------- 5) dt softplus + per-chunk cumsum (shfl scan) ------------
__global__ void cumsum_kernel(const float* __restrict__ A_log,
                              const float* __restrict__ dt_bias){
    int bid = blockIdx.x;            // ((bb*NH)+h)*NC + c
    int c = bid % NC;
    int h = (bid / NC) % NH;
    int bb = bid / (NC*NH);
    int b = bb & 1;
    bool rev = bb >= 2;
    int tid = threadIdx.x;
    int lane = tid & 31, warp = tid >> 5;
    float a = -expf(A_log[h]);
    int t = c*CHUNK_T + tid;
    int tg = rev ? (SEQLEN-1-t) : t;
    int col = (DIP - 2*NH) + (rev ? NH + h : h);
    float raw = __half2float(g_zxh[(size_t)(b*SEQLEN + tg)*DIP + col]);
    float dtv = softplusf(raw + dt_bias[h]);
    g_dt[(size_t)(bb*SEQLEN + t)*NH + h] = dtv;
    float v = dtv * a;
    float sc = v;
    #pragma unroll
    for (int o = 1; o < 32; o <<= 1){
        float u = __shfl_up_sync(0xffffffffu, sc, o);
        if (lane >= o) sc += u;
    }
    __shared__ float wsum[8];
    if (lane == 31) wsum[warp] = sc;
    __syncthreads();
    if (warp == 0 && lane < 8){
        float ws = wsum[lane];
        #pragma unroll
        for (int o = 1; o < 8; o <<= 1){
            float u = __shfl_up_sync(0xffu, ws, o);
            if (lane >= o) ws += u;
        }
        wsum[lane] = ws;
    }
    __syncthreads();
    float base = (warp > 0) ? wsum[warp-1] : 0.f;
    float total = sc + base;
    g_acum[(size_t)bid*CHUNK_T + tid] = total;
    if (tid == CHUNK_T-1) g_csum[bid] = total;
}

// ---------------- 6) chunk states (fp16 mma + ldmatrix) ----------------
#define SMH 88
__global__ void states_kernel(){
    int bid = blockIdx.x;            // (bb*NC+c)*NH + h
    int h = bid % NH;
    int c = (bid / NH) % NC;
    int bb = bid / (NH*NC);
    int b = bb & 1;
    bool rev = bb >= 2;
    int tid = threadIdx.x;
    int lane = tid & 31, warp = tid >> 5;
    int wm = warp >> 2, wn = warp & 3;
    int gid = lane >> 2, qid = lane & 3;
    const int rowsel = lane & 15;
    const int koffA  = (lane >> 4) * 8;
    const int nsel   = (lane & 7) + ((lane >> 4) * 8);
    const int koffB  = ((lane >> 3) & 1) * 8;

    __shared__ __half Ab[64*SMH];
    __shared__ __half Bb[64*SMH];
    __shared__ float dtl[64], decl[64];

    const float* ac = g_acum + ((size_t)(bb*NH + h)*NC + c)*CHUNK_T;
    float cs = g_csum[(bb*NH + h)*NC + c];

    float acc[2][2][4];
    #pragma unroll
    for (int i=0;i<2;i++)
        #pragma unroll
        for (int j=0;j<2;j++)
            #pragma unroll
            for (int r=0;r<4;r++) acc[i][j][r]=0.f;

    for (int ltile = 0; ltile < 4; ltile++){
        if (tid < 64){
            int lc2 = ltile*64 + tid;
            int tgl = c*CHUNK_T + lc2;
            dtl[tid] = g_dt[(size_t)(bb*SEQLEN + tgl)*NH + h];
            decl[tid] = expf(cs - ac[lc2]);
        }
        __syncthreads();
        for (int idx = tid; idx < 64*64; idx += 256){
            int l = idx >> 6, q = idx & 63;
            int tgl = c*CHUNK_T + ltile*64 + l;
            int trow = rev ? (SEQLEN-1 - tgl) : tgl;
            size_t roff = (size_t)(b*SEQLEN + trow)*CONVD;
            float xv = __half2float(g_xch[roff + h*HD + q]);
            float bv = __half2float(g_xch[roff + DI + q]);
            Ab[q*SMH + l] = __float2half(xv * dtl[l]);
            Bb[q*SMH + l] = __float2half(bv * decl[l]);
        }
        __syncthreads();
        #pragma unroll
        for (int ks = 0; ks < 64; ks += 16){
            unsigned a[2][4], bf[2][2];
            #pragma unroll
            for (int i=0;i<2;i++)
                ldsm4(a[i], Ab + (wm*32 + i*16 + rowsel)*SMH + ks + koffA);
            {
                unsigned t0[4];
                ldsm4(t0, Bb + (wn*16 + nsel)*SMH + ks + koffB);
                bf[0][0]=t0[0]; bf[0][1]=t0[1]; bf[1][0]=t0[2]; bf[1][1]=t0[3];
            }
            #pragma unroll
            for (int i=0;i<2;i++)
                #pragma unroll
                for (int j=0;j<2;j++) MMA_F16(acc[i][j], a[i], bf[j]);
        }
        __syncthreads();
    }
    float* sp = g_states + (size_t)bid*(HD*DS);
    #pragma unroll
    for (int i=0;i<2;i++){
        int p = wm*32 + i*16 + gid;
        #pragma unroll
        for (int j=0;j<2;j++){
            int n = wn*16 + j*8 + 2*qid;
            sp[p*DS + n]     = acc[i][j][0];
            sp[p*DS + n + 1] = acc[i][j][1];
            sp[(p+8)*DS + n]     = acc[i][j][2];
            sp[(p+8)*DS + n + 1] = acc[i][j][3];
        }
    }
}

// ---------------- 7) inter-chunk scan (4-way split) ----------------
__global__ void prevscan_kernel(){
    int bid = blockIdx.x;
    int part = bid & 3;
    int bh = bid >> 2;
    int bb = bh / NH, h = bh % NH;
    int tid = threadIdx.x;
    int base = part*1024 + tid;
    float run[4];
    #pragma unroll
    for (int k = 0; k < 4; k++) run[k] = 0.f;
    for (int c = 0; c < NC; c++){
        size_t off = ((size_t)(bb*NC + c)*NH + h)*(HD*DS);
        float e = expf(g_csum[bh*NC + c]);
        #pragma unroll
        for (int k = 0; k < 4; k++){
            int idx = base + k*256;
            g_prevh[off + idx] = __float2half(run[k]);
            run[k] = run[k]*e + g_states[off + idx];
        }
    }
}

// ---------------- 8) Y = Y_diag + Y_off (persistent C tile in smem) --------
__global__ void ydiag_kernel(){
    int bid = blockIdx.x;            // ((bb*NC+c)*NH+h)*4 + lt
    int lt = bid & 3;
    int h  = (bid >> 2) % NH;
    int c  = (bid / (4*NH)) % NC;
    int bb = bid / (4*NH*NC);
    int b = bb & 1;
    bool rev = bb >= 2;
    int tid = threadIdx.x;
    int lane = tid & 31, warp = tid >> 5;
    int wm = warp >> 2, wn = warp & 3;
    int gid = lane >> 2, qid = lane & 3;
    const int rowsel = lane & 15;
    const int koffA  = (lane >> 4) * 8;
    const int nsel   = (lane & 7) + ((lane >> 4) * 8);
    const int koffB  = ((lane >> 3) & 1) * 8;

    __shared__ __half Cb[64*SMH];    // raw C tile, persistent
    __shared__ __half Ab[64*SMH];    // GW scratch
    __shared__ __half Bb[64*SMH];    // prev / Bm / Xd
    __shared__ float acl[64], eacl[64], acs[64], dts[64];

    const float* ac = g_acum + ((size_t)(bb*NH + h)*NC + c)*CHUNK_T;

    if (tid < 64){
        float v = ac[lt*64 + tid];
        acl[tid] = v;
        eacl[tid] = expf(v);
    }

    float acc[2][2][4];
    #pragma unroll
    for (int i=0;i<2;i++)
        #pragma unroll
        for (int j=0;j<2;j++)
            #pragma unroll
            for (int r=0;r<4;r++) acc[i][j][r]=0.f;

    // ---- load raw C into Cb (persistent) and prev into Bb
    {
        size_t poff = ((size_t)(bb*NC + c)*NH + h)*(HD*DS);
        for (int i2 = tid; i2 < 2048; i2 += 256){
            int l = i2 >> 5, c2 = (i2 & 31) * 2;
            int tgl = c*CHUNK_T + lt*64 + l;
            int trl = rev ? (SEQLEN-1 - tgl) : tgl;
            *(__half2*)&Cb[l*SMH + c2] =
                *(const __half2*)&g_xch[(size_t)(b*SEQLEN + trl)*CONVD + DI + DS + c2];
            *(__half2*)&Bb[l*SMH + c2] = *(const __half2*)&g_prevh[poff + l*64 + c2];
        }
        __syncthreads();
        // Y_off with raw C; row-scale acc by exp(acl) afterwards (identical math)
        #pragma unroll
        for (int ks = 0; ks < 64; ks += 16){
            unsigned a[2][4], bf[2][2];
            #pragma unroll
            for (int i=0;i<2;i++)
                ldsm4(a[i], Cb + (wm*32 + i*16 + rowsel)*SMH + ks + koffA);
            {
                unsigned t0[4];
                ldsm4(t0, Bb + (wn*16 + nsel)*SMH + ks + koffB);
                bf[0][0]=t0[0]; bf[0][1]=t0[1]; bf[1][0]=t0[2]; bf[1][1]=t0[3];
            }
            #pragma unroll
            for (int i=0;i<2;i++)
                #pragma unroll
                for (int j=0;j<2;j++) MMA_F16(acc[i][j], a[i], bf[j]);
        }
        #pragma unroll
        for (int i=0;i<2;i++){
            int l0 = wm*32 + i*16 + gid;
            float e0 = eacl[l0], e1 = eacl[l0+8];
            #pragma unroll
            for (int j=0;j<2;j++){
                acc[i][j][0] *= e0; acc[i][j][1] *= e0;
                acc[i][j][2] *= e1; acc[i][j][3] *= e1;
            }
        }
        __syncthreads();
    }

    // ---- Y_diag over s-tiles <= lt (C stays in Cb)
    for (int st = 0; st <= lt; st++){
        if (tid < 64){
            acs[tid] = ac[st*64 + tid];
            dts[tid] = g_dt[(size_t)(bb*SEQLEN + c*CHUNK_T + st*64 + tid)*NH + h];
        }
        // load Bm(st) into Bb
        for (int i2 = tid; i2 < 2048; i2 += 256){
            int r = i2 >> 5, c2 = (i2 & 31) * 2;
            int tgs = c*CHUNK_T + st*64 + r;
            int trs = rev ? (SEQLEN-1 - tgs) : tgs;
            *(__half2*)&Bb[r*SMH + c2] =
                *(const __half2*)&g_xch[(size_t)(b*SEQLEN + trs)*CONVD + DI + c2];
        }
        __syncthreads();
        // G[l,s] = C . Bm^T  (A from persistent Cb)
        float g[2][2][4];
        #pragma unroll
        for (int i=0;i<2;i++)
            #pragma unroll
            for (int j=0;j<2;j++)
                #pragma unroll
                for (int r=0;r<4;r++) g[i][j][r]=0.f;
        #pragma unroll
        for (int ks = 0; ks < 64; ks += 16){
            unsigned a[2][4], bf[2][2];
            #pragma unroll
            for (int i=0;i<2;i++)
                ldsm4(a[i], Cb + (wm*32 + i*16 + rowsel)*SMH + ks + koffA);
            {
                unsigned t0[4];
                ldsm4(t0, Bb + (wn*16 + nsel)*SMH + ks + koffB);
                bf[0][0]=t0[0]; bf[0][1]=t0[1]; bf[1][0]=t0[2]; bf[1][1]=t0[3];
            }
            #pragma unroll
            for (int i=0;i<2;i++)
                #pragma unroll
                for (int j=0;j<2;j++) MMA_F16(g[i][j], a[i], bf[j]);
        }
        __syncthreads();
        bool diag = (st == lt);
        #pragma unroll
        for (int i=0;i<2;i++){
            int l0 = wm*32 + i*16 + gid;
            #pragma unroll
            for (int j=0;j<2;j++){
                int s0 = wn*16 + j*8 + 2*qid;
                float al0 = acl[l0], al1 = acl[l0+8];
                float w00 = (diag && s0   > l0) ? 0.f : expf(al0 - acs[s0]);
                float w01 = (diag && s0+1 > l0) ? 0.f : expf(al0 - acs[s0+1]);
                float w10 = (diag && s0   > l0+8) ? 0.f : expf(al1 - acs[s0]);
                float w11 = (diag && s0+1 > l0+8) ? 0.f : expf(al1 - acs[s0+1]);
                Ab[l0*SMH + s0]       = __float2half(g[i][j][0]*w00);
                Ab[l0*SMH + s0+1]     = __float2half(g[i][j][1]*w01);
                Ab[(l0+8)*SMH + s0]   = __float2half(g[i][j][2]*w10);
                Ab[(l0+8)*SMH + s0+1] = __float2half(g[i][j][3]*w11);
            }
        }
        // Xd^T into Bb (overwrites Bm — G already consumed)
        for (int idx = tid; idx < 64*64; idx += 256){
            int s = idx >> 6, p = idx & 63;
            int tgs = c*CHUNK_T + st*64 + s;
            int trs = rev ? (SEQLEN-1 - tgs) : tgs;
            float xv = __half2float(g_xch[(size_t)(b*SEQLEN + trs)*CONVD + h*HD + p]);
            Bb[p*SMH + s] = __float2half(xv * dts[s]);
        }
        __syncthreads();
        #pragma unroll
        for (int ks = 0; ks < 64; ks += 16){
            unsigned a[2][4], bf[2][2];
            #pragma unroll
            for (int i=0;i<2;i++)
                ldsm4(a[i], Ab + (wm*32 + i*16 + rowsel)*SMH + ks + koffA);
            {
                unsigned t0[4];
                ldsm4(t0, Bb + (wn*16 + nsel)*SMH + ks + koffB);
                bf[0][0]=t0[0]; bf[0][1]=t0[1]; bf[1][0]=t0[2]; bf[1][1]=t0[3];
            }
            #pragma unroll
            for (int i=0;i<2;i++)
                #pragma unroll
                for (int j=0;j<2;j++) MMA_F16(acc[i][j], a[i], bf[j]);
        }
        __syncthreads();
    }

    #pragma unroll
    for (int i=0;i<2;i++){
        int l = wm*32 + i*16 + gid;
        int tg0 = c*CHUNK_T + lt*64 + l;
        #pragma unroll
        for (int j=0;j<2;j++){
            int pc = h*HD + wn*16 + j*8 + 2*qid;
            size_t o0 = (size_t)(bb*SEQLEN + tg0)*DI + pc;
            size_t o1 = (size_t)(bb*SEQLEN + tg0 + 8)*DI + pc;
            *(__half2*)&g_yssdh[o0] = __floats2half2_rn(acc[i][j][0], acc[i][j][1]);
            *(__half2*)&g_yssdh[o1] = __floats2half2_rn(acc[i][j][2], acc[i][j][3]);
        }
    }
}

// ---------------- 9) fc_D (fp16 inputs) ----------------
__global__ void fcd_kernel(const float* __restrict__ fw){
    __shared__ float ws[NH][132];
    int r0 = blockIdx.x * 64;
    int tid = threadIdx.x;
    int rl = tid >> 2;
    int lj = tid & 3;
    float acc[6] = {0.f,0.f,0.f,0.f,0.f,0.f};
    for (int k0 = 0; k0 < DI; k0 += 128){
        for (int i = tid; i < NH*128; i += 256)
            ws[i>>7][i&127] = fw[(size_t)(i>>7)*DI + k0 + (i&127)];
        __syncthreads();
        const __half2* xr = (const __half2*)&g_xch[(size_t)(r0+rl)*CONVD + k0];
        #pragma unroll 16
        for (int kk = 0; kk < 64; kk += 2){
            float2 x0 = __half22float2(xr[kk]);
            float2 x1 = __half22float2(xr[kk+1]);
            #pragma unroll
            for (int hh = 0; hh < 6; hh++){
                int h = lj*6 + hh;
                acc[hh] += x0.x*ws[h][kk*2] + x0.y*ws[h][kk*2+1]
                         + x1.x*ws[h][kk*2+2] + x1.y*ws[h][kk*2+3];
            }
        }
        __syncthreads();
    }
    #pragma unroll
    for (int hh = 0; hh < 6; hh++)
        g_dterm[(size_t)(r0+rl)*NH + lj*6 + hh] = acc[hh];
}

// ---------------- 10) combine + gate + RMSNorm (half2 vectorized) ----------
__global__ void combine_kernel(const float* __restrict__ Dv,
                               const float* __restrict__ rms_w){
    __shared__ float ybuf[DI];
    __shared__ float red[8];
    int bl = blockIdx.x;
    int b = bl / SEQLEN, t = bl % SEQLEN;
    int tid = threadIdx.x;
    float ss = 0.f;
    for (int d = tid*2; d < DI; d += 512){
        float2 yf = make_float2(0.f, 0.f), yb = make_float2(0.f, 0.f);
        if (t > 0)
            yf = __half22float2(*(const __half2*)&g_yssdh[(size_t)(b*SEQLEN + t - 1)*DI + d]);
        if (t <= SEQLEN-2)
            yb = __half22float2(*(const __half2*)&g_yssdh[(size_t)((2+b)*SEQLEN + (SEQLEN-2 - t))*DI + d]);
        float2 xo = __half22float2(*(const __half2*)&g_xch[(size_t)bl*CONVD + d]);
        float2 z  = __half22float2(*(const __half2*)&g_zxh[(size_t)bl*DIP + d]);
        int h = d >> 6;
        float dterm = g_dterm[(size_t)bl*NH + h] + Dv[h];
        float y0 = (yf.x + yb.x + xo.x*dterm) * siluf(z.x);
        float y1 = (yf.y + yb.y + xo.y*dterm) * siluf(z.y);
        ybuf[d] = y0; ybuf[d+1] = y1;
        ss += y0*y0 + y1*y1;
    }
    float tot = blockReduce256(ss, red);
    float inv = rsqrtf(tot/DI + EPSV);
    __syncthreads();
    for (int d = tid*2; d < DI; d += 512){
        float2 rw = *(const float2*)&rms_w[d];
        *(__half2*)&g_ynh[(size_t)bl*DI + d] =
            __floats2half2_rn(ybuf[d]*inv*rw.x, ybuf[d+1]*inv*rw.y);
    }
}

// ---------------- launch ----------------
extern "C" void kernel_launch(void* const* d_in, const int* in_sizes, int n_in,
                              void* d_out, int out_size){
    const float* x          = (const float*)d_in[0];
    const float* ln_w       = (const float*)d_in[1];
    const float* ln_b       = (const float*)d_in[2];
    const float* in_proj_w  = (const float*)d_in[3];
    const float* conv_w     = (const float*)d_in[4];
    const float* conv_b     = (const float*)d_in[5];
    const float* dt_bias    = (const float*)d_in[6];
    const float* A_log      = (const float*)d_in[7];
    const float* Dv         = (const float*)d_in[8];
    const float* fc_D_w     = (const float*)d_in[9];
    const float* rms_w      = (const float*)d_in[10];
    const float* out_proj_w = (const float*)d_in[11];
    float* out = (float*)d_out;

    __half *uh, *ynh, *wah, *woh, *zxh;
    cudaGetSymbolAddress((void**)&uh,  g_uh);
    cudaGetSymbolAddress((void**)&ynh, g_ynh);
    cudaGetSymbolAddress((void**)&wah, g_wah);
    cudaGetSymbolAddress((void**)&woh, g_woh);
    cudaGetSymbolAddress((void**)&zxh, g_zxh);

    static bool attr_set = false;
    const int gsmem   = GSTH*2*128*SMSH*(int)sizeof(__half);       // 81920 B
    const int gsmem64 = GSTH*(128+64)*SMSH*(int)sizeof(__half);    // 61440 B
    if (!attr_set){
        cudaFuncSetAttribute(gemm_h, cudaFuncAttributeMaxDynamicSharedMemorySize, gsmem);
        cudaFuncSetAttribute(gemm_h_n64, cudaFuncAttributeMaxDynamicSharedMemorySize, gsmem64);
        attr_set = true;
    }

    wconv_kernel<<<(DIP*DM + 255)/256, 256>>>(in_proj_w, out_proj_w);
    ln_kernel<<<BL, 256>>>(x, ln_w, ln_b);

    // in_proj -> fp16 zx
    gemm_h<<<dim3((DIP+127)/128, BL/128), 256, gsmem>>>(uh, DM, wah, DM,
        nullptr, nullptr, zxh, DIP, BL, DIP, DM);

    conv_kernel<<<dim3(CONVD/128, SEQLEN/CTS, BATCH), 256>>>(conv_w, conv_b);
    cumsum_kernel<<<NBB*NH*NC, 256>>>(A_log, dt_bias);
    states_kernel<<<NBB*NC*NH, 256>>>();
    prevscan_kernel<<<NBB*NH*4, 256>>>();
    ydiag_kernel<<<NBB*NC*NH*4, 256>>>();
    fcd_kernel<<<BL/64, 256>>>(fc_D_w);
    combine_kernel<<<BL, 256>>>(Dv, rms_w);

    // out_proj + residual -> fp32 out
    gemm_h_n64<<<dim3(DM/64, BL/128), 256, gsmem64>>>(ynh, DI, woh, DI,
        x, out, DM, BL, DM, DI);
}

// round 17
// speedup vs baseline: 1.1783x; 1.0086x over previous
#include <cuda_runtime.h>
#include <cuda_fp16.h>
#include <math.h>
#include <stdint.h>

// ---------------- constants ----------------
#define BATCH   2
#define SEQLEN  4096
#define BL      (BATCH*SEQLEN)          // 8192 rows
#define DM      768
#define DI      1536
#define NH      24
#define HD      64
#define DS      64
#define DCONV   7
#define CONVD   (DI + 2*DS)             // 1664
#define DIP     (2*DI + 2*DS + 2*NH)    // 3248
#define CHUNK_T 256
#define NC      (SEQLEN/CHUNK_T)        // 16
#define NBB     (2*BATCH)               // 4 direction-batches
#define EPSV    1e-5f

// ---------------- scratch ----------------
__device__ __half g_zxh[(size_t)BL*DIP];
__device__ __half g_xch[(size_t)BL*CONVD];
__device__ float g_dt[(size_t)NBB*SEQLEN*NH];
__device__ float g_acum[(size_t)NBB*NH*NC*CHUNK_T];
__device__ float g_csum[(size_t)NBB*NH*NC];
__device__ float g_states[(size_t)NBB*NC*NH*HD*DS];
__device__ __half g_prevh[(size_t)NBB*NC*NH*HD*DS];
__device__ __half g_yssdh[(size_t)NBB*SEQLEN*DI];
__device__ float g_dterm[(size_t)BL*NH];
__device__ __half g_uh[(size_t)BL*DM];
__device__ __half g_ynh[(size_t)BL*DI];
__device__ __half g_wah[(size_t)DIP*DM];
__device__ __half g_woh[(size_t)DM*DI];

// ---------------- helpers ----------------
__device__ __forceinline__ float softplusf(float x){
    return (x > 20.f) ? x : log1pf(expf(x));
}
__device__ __forceinline__ float siluf(float x){
    return x / (1.f + expf(-x));
}
#define MMA_F16(acc, a, b) \
    asm volatile("mma.sync.aligned.m16n8k16.row.col.f32.f16.f16.f32 " \
        "{%0,%1,%2,%3},{%4,%5,%6,%7},{%8,%9},{%0,%1,%2,%3};" \
        : "+f"(acc[0]),"+f"(acc[1]),"+f"(acc[2]),"+f"(acc[3]) \
        : "r"(a[0]),"r"(a[1]),"r"(a[2]),"r"(a[3]),"r"(b[0]),"r"(b[1]))

__device__ __forceinline__ void ldsm4(unsigned* r, const __half* p){
    unsigned a = (unsigned)__cvta_generic_to_shared(p);
    asm volatile("ldmatrix.sync.aligned.m8n8.x4.shared.b16 {%0,%1,%2,%3}, [%4];"
        : "=r"(r[0]),"=r"(r[1]),"=r"(r[2]),"=r"(r[3]) : "r"(a));
}

__device__ __forceinline__ void cp16(void* dst, const void* src, bool p){
    unsigned d = (unsigned)__cvta_generic_to_shared(dst);
    int sz = p ? 16 : 0;
    asm volatile("cp.async.cg.shared.global [%0], [%1], 16, %2;\n"
                 :: "r"(d), "l"(src), "r"(sz));
}
__device__ __forceinline__ void cp_commit(){ asm volatile("cp.async.commit_group;\n"); }
__device__ __forceinline__ void cp_wait2(){ asm volatile("cp.async.wait_group 2;\n"); }

__device__ __forceinline__ float blockReduce256(float v, float* red){
    int tid = threadIdx.x;
    int lane = tid & 31, w = tid >> 5;
    #pragma unroll
    for (int o = 16; o > 0; o >>= 1) v += __shfl_xor_sync(0xffffffffu, v, o);
    if (lane == 0) red[w] = v;
    __syncthreads();
    float r = (lane < 8) ? red[lane] : 0.f;
    #pragma unroll
    for (int o = 4; o > 0; o >>= 1) r += __shfl_xor_sync(0xffffffffu, r, o);
    r = __shfl_sync(0xffffffffu, r, 0);
    return r;
}

// ---------------- 0) weight convert to fp16 ----------------
__global__ void wconv_kernel(const float* __restrict__ wi,
                             const float* __restrict__ wo){
    int i = blockIdx.x*256 + threadIdx.x;
    if (i < DIP*DM) g_wah[i] = __float2half(wi[i]);
    if (i < DM*DI)  g_woh[i] = __float2half(wo[i]);
}

// ---------------- 1) LayerNorm (emits fp16) ----------------
__global__ void ln_kernel(const float* __restrict__ x,
                          const float* __restrict__ w,
                          const float* __restrict__ b){
    __shared__ float red[8];
    int row = blockIdx.x;
    const float* xr = x + (size_t)row*DM;
    int tid = threadIdx.x;
    float s = 0.f;
    for (int i = tid; i < DM; i += 256) s += xr[i];
    float mu = blockReduce256(s, red) / DM;
    __syncthreads();
    float v = 0.f;
    for (int i = tid; i < DM; i += 256){ float d = xr[i]-mu; v += d*d; }
    float var = blockReduce256(v, red) / DM;
    float inv = rsqrtf(var + EPSV);
    for (int i = tid; i < DM; i += 256)
        g_uh[(size_t)row*DM + i] = __float2half((xr[i]-mu)*inv*w[i] + b[i]);
}

// ---------------- fp16 GEMM, 4-stage cp.async, m16n8k16, ldmatrix ----------
#define SMSH 40
#define GSTH 4
__global__ __launch_bounds__(256, 2)
void gemm_h(const __half* __restrict__ A, int lda,
            const __half* __restrict__ B, int ldb,
            const float* __restrict__ R,
            float* __restrict__ C, __half* __restrict__ Ch, int ldc,
            int M, int N, int K){
    extern __shared__ __half smh[];
    __half* AsB = smh;
    __half* BsB = smh + GSTH*128*SMSH;
    const int tid  = threadIdx.x;
    const int lane = tid & 31;
    const int warp = tid >> 5;
    const int wm = warp >> 2;
    const int wn = warp & 3;
    const int m0 = blockIdx.y * 128;
    const int n0 = blockIdx.x * 128;
    const int rowsel = lane & 15;
    const int koffA  = (lane >> 4) * 8;
    const int nsel   = (lane & 7) + ((lane >> 4) * 8);
    const int koffB  = ((lane >> 3) & 1) * 8;

    float acc[4][4][4];
    #pragma unroll
    for (int i=0;i<4;i++)
        #pragma unroll
        for (int j=0;j<4;j++)
            #pragma unroll
            for (int r=0;r<4;r++) acc[i][j][r]=0.f;

    const int nk = K >> 5;
    const int c0r = tid >> 2,  c0q = tid & 3;
    const int c1r = (tid+256) >> 2, c1q = tid & 3;

    const __half* ApA = A + (size_t)(m0 + c0r)*lda + c0q*8;
    const __half* ApB = A + (size_t)(m0 + c1r)*lda + c1q*8;
    const int bn0 = n0 + c0r, bn1 = n0 + c1r;
    const __half* BpA = B + (size_t)bn0*ldb + c0q*8;
    const __half* BpB = B + (size_t)bn1*ldb + c1q*8;
    const bool bokA = bn0 < N, bokB = bn1 < N;

    #pragma unroll
    for (int s = 0; s < GSTH-1; s++){
        int ko = s << 5;
        __half* as = AsB + s*(128*SMSH);
        __half* bs = BsB + s*(128*SMSH);
        cp16(as + c0r*SMSH + c0q*8, ApA + ko, true);
        cp16(as + c1r*SMSH + c1q*8, ApB + ko, true);
        cp16(bs + c0r*SMSH + c0q*8, BpA + ko, bokA);
        cp16(bs + c1r*SMSH + c1q*8, BpB + ko, bokB);
        cp_commit();
    }

    for (int kt = 0; kt < nk; kt++){
        cp_wait2();
        __syncthreads();
        int kn = kt + GSTH - 1;
        if (kn < nk){
            int ko = kn << 5;
            int stg = kn % GSTH;
            __half* as = AsB + stg*(128*SMSH);
            __half* bs = BsB + stg*(128*SMSH);
            cp16(as + c0r*SMSH + c0q*8, ApA + ko, true);
            cp16(as + c1r*SMSH + c1q*8, ApB + ko, true);
            cp16(bs + c0r*SMSH + c0q*8, BpA + ko, bokA);
            cp16(bs + c1r*SMSH + c1q*8, BpB + ko, bokB);
        }
        cp_commit();

        const __half* As = AsB + (kt % GSTH)*(128*SMSH);
        const __half* Bs = BsB + (kt % GSTH)*(128*SMSH);
        #pragma unroll
        for (int ks = 0; ks < 32; ks += 16){
            unsigned a[4][4], bfr[4][2];
            #pragma unroll
            for (int i=0;i<4;i++)
                ldsm4(a[i], As + (wm*64 + i*16 + rowsel)*SMSH + ks + koffA);
            {
                unsigned t0[4], t1[4];
                ldsm4(t0, Bs + (wn*32 + nsel)*SMSH + ks + koffB);
                ldsm4(t1, Bs + (wn*32 + 16 + nsel)*SMSH + ks + koffB);
                bfr[0][0]=t0[0]; bfr[0][1]=t0[1]; bfr[1][0]=t0[2]; bfr[1][1]=t0[3];
                bfr[2][0]=t1[0]; bfr[2][1]=t1[1]; bfr[3][0]=t1[2]; bfr[3][1]=t1[3];
            }
            #pragma unroll
            for (int i=0;i<4;i++)
                #pragma unroll
                for (int j=0;j<4;j++) MMA_F16(acc[i][j], a[i], bfr[j]);
        }
    }

    #pragma unroll
    for (int i=0;i<4;i++){
        int r0 = m0 + wm*64 + i*16 + (lane>>2);
        #pragma unroll
        for (int j=0;j<4;j++){
            int cb = n0 + wn*32 + j*8;
            if (cb < N){
                int cc = cb + 2*(lane & 3);
                size_t o0 = (size_t)r0*ldc + cc;
                size_t o1 = (size_t)(r0+8)*ldc + cc;
                if (Ch){
                    *(__half2*)&Ch[o0] = __floats2half2_rn(acc[i][j][0], acc[i][j][1]);
                    *(__half2*)&Ch[o1] = __floats2half2_rn(acc[i][j][2], acc[i][j][3]);
                } else {
                    float v0 = acc[i][j][0], v1 = acc[i][j][1];
                    float v2 = acc[i][j][2], v3 = acc[i][j][3];
                    if (R){ v0 += R[o0]; v1 += R[o0+1]; v2 += R[o1]; v3 += R[o1+1]; }
                    C[o0] = v0; C[o0+1] = v1; C[o1] = v2; C[o1+1] = v3;
                }
            }
        }
    }
}

// ---------------- fp16 GEMM, 128xM x 64xN tile (out_proj + residual) -------
__global__ __launch_bounds__(256, 2)
void gemm_h_n64(const __half* __restrict__ A, int lda,
                const __half* __restrict__ B, int ldb,
                const float* __restrict__ R,
                float* __restrict__ C, int ldc,
                int M, int N, int K){
    extern __shared__ __half smh[];
    __half* AsB = smh;
    __half* BsB = smh + GSTH*128*SMSH;
    const int tid  = threadIdx.x;
    const int lane = tid & 31;
    const int warp = tid >> 5;
    const int wm = warp >> 2;
    const int wn = warp & 3;
    const int m0 = blockIdx.y * 128;
    const int n0 = blockIdx.x * 64;
    const int rowsel = lane & 15;
    const int koffA  = (lane >> 4) * 8;
    const int nsel   = (lane & 7) + ((lane >> 4) * 8);
    const int koffB  = ((lane >> 3) & 1) * 8;

    float acc[4][2][4];
    #pragma unroll
    for (int i=0;i<4;i++)
        #pragma unroll
        for (int j=0;j<2;j++)
            #pragma unroll
            for (int r=0;r<4;r++) acc[i][j][r]=0.f;

    const int nk = K >> 5;
    const int c0r = tid >> 2,  c0q = tid & 3;
    const int c1r = (tid+256) >> 2, c1q = tid & 3;

    const __half* ApA = A + (size_t)(m0 + c0r)*lda + c0q*8;
    const __half* ApB = A + (size_t)(m0 + c1r)*lda + c1q*8;
    const __half* Bp  = B + (size_t)(n0 + c0r)*ldb + c0q*8;
    const bool brow = c0r < 64;

    #pragma unroll
    for (int s = 0; s < GSTH-1; s++){
        int ko = s << 5;
        __half* as = AsB + s*(128*SMSH);
        __half* bs = BsB + s*(64*SMSH);
        cp16(as + c0r*SMSH + c0q*8, ApA + ko, true);
        cp16(as + c1r*SMSH + c1q*8, ApB + ko, true);
        if (brow) cp16(bs + c0r*SMSH + c0q*8, Bp + ko, true);
        cp_commit();
    }

    for (int kt = 0; kt < nk; kt++){
        cp_wait2();
        __syncthreads();
        int kn = kt + GSTH - 1;
        if (kn < nk){
            int ko = kn << 5;
            int stg = kn % GSTH;
            __half* as = AsB + stg*(128*SMSH);
            __half* bs = BsB + stg*(64*SMSH);
            cp16(as + c0r*SMSH + c0q*8, ApA + ko, true);
            cp16(as + c1r*SMSH + c1q*8, ApB + ko, true);
            if (brow) cp16(bs + c0r*SMSH + c0q*8, Bp + ko, true);
        }
        cp_commit();

        const __half* As = AsB + (kt % GSTH)*(128*SMSH);
        const __half* Bs = BsB + (kt % GSTH)*(64*SMSH);
        #pragma unroll
        for (int ks = 0; ks < 32; ks += 16){
            unsigned a[4][4], bfr[2][2];
            #pragma unroll
            for (int i=0;i<4;i++)
                ldsm4(a[i], As + (wm*64 + i*16 + rowsel)*SMSH + ks + koffA);
            {
                unsigned t0[4];
                ldsm4(t0, Bs + (wn*16 + nsel)*SMSH + ks + koffB);
                bfr[0][0]=t0[0]; bfr[0][1]=t0[1]; bfr[1][0]=t0[2]; bfr[1][1]=t0[3];
            }
            #pragma unroll
            for (int i=0;i<4;i++)
                #pragma unroll
                for (int j=0;j<2;j++) MMA_F16(acc[i][j], a[i], bfr[j]);
        }
    }

    #pragma unroll
    for (int i=0;i<4;i++){
        int r0 = m0 + wm*64 + i*16 + (lane>>2);
        #pragma unroll
        for (int j=0;j<2;j++){
            int cc = n0 + wn*16 + j*8 + 2*(lane & 3);
            size_t o0 = (size_t)r0*ldc + cc;
            size_t o1 = (size_t)(r0+8)*ldc + cc;
            float v0 = acc[i][j][0], v1 = acc[i][j][1];
            float v2 = acc[i][j][2], v3 = acc[i][j][3];
            if (R){ v0 += R[o0]; v1 += R[o0+1]; v2 += R[o1]; v3 += R[o1+1]; }
            C[o0] = v0; C[o0+1] = v1; C[o1] = v2; C[o1+1] = v3;
        }
    }
}

// ---------------- 4) conv: half2 channel pairs ----------------
#define CTS 32
__global__ void conv_kernel(const float* __restrict__ cw,
                            const float* __restrict__ cb){
    __shared__ __half2 s[CTS+6][64];
    __shared__ __half2 w[7][64];
    __shared__ __half2 bias[64];
    int ch0 = blockIdx.x * 128;
    int t0  = blockIdx.y * CTS;
    int b   = blockIdx.z;
    int tid = threadIdx.x;
    for (int i = tid; i < 7*64; i += 256){
        int j = i >> 6, cp = i & 63;
        w[j][cp] = __floats2half2_rn(cw[(size_t)(ch0+cp*2)*DCONV + j],
                                     cw[(size_t)(ch0+cp*2+1)*DCONV + j]);
    }
    if (tid < 64) bias[tid] = __floats2half2_rn(cb[ch0 + tid*2], cb[ch0 + tid*2+1]);
    for (int i = tid; i < (CTS+6)*64; i += 256){
        int tt = t0 - 6 + (i >> 6);
        int cp = i & 63;
        s[i>>6][cp] = (tt >= 0)
            ? *(const __half2*)&g_zxh[(size_t)(b*SEQLEN + tt)*DIP + DI + ch0 + cp*2]
            : __floats2half2_rn(0.f, 0.f);
    }
    __syncthreads();
    #pragma unroll
    for (int k = 0; k < 8; k++){
        int o = tid + k*256;
        int tl = o >> 6, cp = o & 63;
        float2 acc = __half22float2(bias[cp]);
        #pragma unroll
        for (int j = 0; j < 7; j++){
            float2 wv = __half22float2(w[j][cp]);
            float2 sv = __half22float2(s[tl+j][cp]);
            acc.x += wv.x*sv.x; acc.y += wv.y*sv.y;
        }
        *(__half2*)&g_xch[(size_t)(b*SEQLEN + t0 + tl)*CONVD + ch0 + cp*2]
            = __floats2half2_rn(siluf(acc.x), siluf(acc.y));
    }
}

// ---------------- 5) dt softplus + per-chunk cumsum (shfl scan) ------------
__global__ void cumsum_kernel(const float* __restrict__ A_log,
                              const float* __restrict__ dt_bias){
    int bid = blockIdx.x;            // ((bb*NH)+h)*NC + c
    int c = bid % NC;
    int h = (bid / NC) % NH;
    int bb = bid / (NC*NH);
    int b = bb & 1;
    bool rev = bb >= 2;
    int tid = threadIdx.x;
    int lane = tid & 31, warp = tid >> 5;
    float a = -expf(A_log[h]);
    int t = c*CHUNK_T + tid;
    int tg = rev ? (SEQLEN-1-t) : t;
    int col = (DIP - 2*NH) + (rev ? NH + h : h);
    float raw = __half2float(g_zxh[(size_t)(b*SEQLEN + tg)*DIP + col]);
    float dtv = softplusf(raw + dt_bias[h]);
    g_dt[(size_t)(bb*SEQLEN + t)*NH + h] = dtv;
    float v = dtv * a;
    float sc = v;
    #pragma unroll
    for (int o = 1; o < 32; o <<= 1){
        float u = __shfl_up_sync(0xffffffffu, sc, o);
        if (lane >= o) sc += u;
    }
    __shared__ float wsum[8];
    if (lane == 31) wsum[warp] = sc;
    __syncthreads();
    if (warp == 0 && lane < 8){
        float ws = wsum[lane];
        #pragma unroll
        for (int o = 1; o < 8; o <<= 1){
            float u = __shfl_up_sync(0xffu, ws, o);
            if (lane >= o) ws += u;
        }
        wsum[lane] = ws;
    }
    __syncthreads();
    float base = (warp > 0) ? wsum[warp-1] : 0.f;
    float total = sc + base;
    g_acum[(size_t)bid*CHUNK_T + tid] = total;
    if (tid == CHUNK_T-1) g_csum[bid] = total;
}

// ---------------- 6) chunk states (fp16 mma + ldmatrix) ----------------
#define SMH 88
__global__ void states_kernel(){
    int bid = blockIdx.x;            // (bb*NC+c)*NH + h
    int h = bid % NH;
    int c = (bid / NH) % NC;
    int bb = bid / (NH*NC);
    int b = bb & 1;
    bool rev = bb >= 2;
    int tid = threadIdx.x;
    int lane = tid & 31, warp = tid >> 5;
    int wm = warp >> 2, wn = warp & 3;
    int gid = lane >> 2, qid = lane & 3;
    const int rowsel = lane & 15;
    const int koffA  = (lane >> 4) * 8;
    const int nsel   = (lane & 7) + ((lane >> 4) * 8);
    const int koffB  = ((lane >> 3) & 1) * 8;

    __shared__ __half Ab[64*SMH];
    __shared__ __half Bb[64*SMH];
    __shared__ float dtl[64], decl[64];

    const float* ac = g_acum + ((size_t)(bb*NH + h)*NC + c)*CHUNK_T;
    float cs = g_csum[(bb*NH + h)*NC + c];

    float acc[2][2][4];
    #pragma unroll
    for (int i=0;i<2;i++)
        #pragma unroll
        for (int j=0;j<2;j++)
            #pragma unroll
            for (int r=0;r<4;r++) acc[i][j][r]=0.f;

    for (int ltile = 0; ltile < 4; ltile++){
        if (tid < 64){
            int lc2 = ltile*64 + tid;
            int tgl = c*CHUNK_T + lc2;
            dtl[tid] = g_dt[(size_t)(bb*SEQLEN + tgl)*NH + h];
            decl[tid] = expf(cs - ac[lc2]);
        }
        __syncthreads();
        for (int idx = tid; idx < 64*64; idx += 256){
            int l = idx >> 6, q = idx & 63;
            int tgl = c*CHUNK_T + ltile*64 + l;
            int trow = rev ? (SEQLEN-1 - tgl) : tgl;
            size_t roff = (size_t)(b*SEQLEN + trow)*CONVD;
            float xv = __half2float(g_xch[roff + h*HD + q]);
            float bv = __half2float(g_xch[roff + DI + q]);
            Ab[q*SMH + l] = __float2half(xv * dtl[l]);
            Bb[q*SMH + l] = __float2half(bv * decl[l]);
        }
        __syncthreads();
        #pragma unroll
        for (int ks = 0; ks < 64; ks += 16){
            unsigned a[2][4], bf[2][2];
            #pragma unroll
            for (int i=0;i<2;i++)
                ldsm4(a[i], Ab + (wm*32 + i*16 + rowsel)*SMH + ks + koffA);
            {
                unsigned t0[4];
                ldsm4(t0, Bb + (wn*16 + nsel)*SMH + ks + koffB);
                bf[0][0]=t0[0]; bf[0][1]=t0[1]; bf[1][0]=t0[2]; bf[1][1]=t0[3];
            }
            #pragma unroll
            for (int i=0;i<2;i++)
                #pragma unroll
                for (int j=0;j<2;j++) MMA_F16(acc[i][j], a[i], bf[j]);
        }
        __syncthreads();
    }
    float* sp = g_states + (size_t)bid*(HD*DS);
    #pragma unroll
    for (int i=0;i<2;i++){
        int p = wm*32 + i*16 + gid;
        #pragma unroll
        for (int j=0;j<2;j++){
            int n = wn*16 + j*8 + 2*qid;
            *(float2*)&sp[p*DS + n]     = make_float2(acc[i][j][0], acc[i][j][1]);
            *(float2*)&sp[(p+8)*DS + n] = make_float2(acc[i][j][2], acc[i][j][3]);
        }
    }
}

// ---------------- 7) inter-chunk scan (4-way split) ----------------
__global__ void prevscan_kernel(){
    int bid = blockIdx.x;
    int part = bid & 3;
    int bh = bid >> 2;
    int bb = bh / NH, h = bh % NH;
    int tid = threadIdx.x;
    int base = part*1024 + tid;
    float run[4];
    #pragma unroll
    for (int k = 0; k < 4; k++) run[k] = 0.f;
    for (int c = 0; c < NC; c++){
        size_t off = ((size_t)(bb*NC + c)*NH + h)*(HD*DS);
        float e = expf(g_csum[bh*NC + c]);
        #pragma unroll
        for (int k = 0; k < 4; k++){
            int idx = base + k*256;
            g_prevh[off + idx] = __float2half(run[k]);
            run[k] = run[k]*e + g_states[off + idx];
        }
    }
}

// ---------------- 8) Y = Y_diag + Y_off (persistent C tile in smem) --------
__global__ void ydiag_kernel(){
    int bid = blockIdx.x;            // ((bb*NC+c)*NH+h)*4 + lt
    int lt = bid & 3;
    int h  = (bid >> 2) % NH;
    int c  = (bid / (4*NH)) % NC;
    int bb = bid / (4*NH*NC);
    int b = bb & 1;
    bool rev = bb >= 2;
    int tid = threadIdx.x;
    int lane = tid & 31, warp = tid >> 5;
    int wm = warp >> 2, wn = warp & 3;
    int gid = lane >> 2, qid = lane & 3;
    const int rowsel = lane & 15;
    const int koffA  = (lane >> 4) * 8;
    const int nsel   = (lane & 7) + ((lane >> 4) * 8);
    const int koffB  = ((lane >> 3) & 1) * 8;

    __shared__ __half Cb[64*SMH];    // raw C tile, persistent
    __shared__ __half Ab[64*SMH];    // GW scratch
    __shared__ __half Bb[64*SMH];    // prev / Bm / Xd
    __shared__ float acl[64], eacl[64], acs[64], dts[64];

    const float* ac = g_acum + ((size_t)(bb*NH + h)*NC + c)*CHUNK_T;

    if (tid < 64){
        float v = ac[lt*64 + tid];
        acl[tid] = v;
        eacl[tid] = expf(v);
    }

    float acc[2][2][4];
    #pragma unroll
    for (int i=0;i<2;i++)
        #pragma unroll
        for (int j=0;j<2;j++)
            #pragma unroll
            for (int r=0;r<4;r++) acc[i][j][r]=0.f;

    // ---- load raw C into Cb (persistent) and prev into Bb
    {
        size_t poff = ((size_t)(bb*NC + c)*NH + h)*(HD*DS);
        for (int i2 = tid; i2 < 2048; i2 += 256){
            int l = i2 >> 5, c2 = (i2 & 31) * 2;
            int tgl = c*CHUNK_T + lt*64 + l;
            int trl = rev ? (SEQLEN-1 - tgl) : tgl;
            *(__half2*)&Cb[l*SMH + c2] =
                *(const __half2*)&g_xch[(size_t)(b*SEQLEN + trl)*CONVD + DI + DS + c2];
            *(__half2*)&Bb[l*SMH + c2] = *(const __half2*)&g_prevh[poff + l*64 + c2];
        }
        __syncthreads();
        #pragma unroll
        for (int ks = 0; ks < 64; ks += 16){
            unsigned a[2][4], bf[2][2];
            #pragma unroll
            for (int i=0;i<2;i++)
                ldsm4(a[i], Cb + (wm*32 + i*16 + rowsel)*SMH + ks + koffA);
            {
                unsigned t0[4];
                ldsm4(t0, Bb + (wn*16 + nsel)*SMH + ks + koffB);
                bf[0][0]=t0[0]; bf[0][1]=t0[1]; bf[1][0]=t0[2]; bf[1][1]=t0[3];
            }
            #pragma unroll
            for (int i=0;i<2;i++)
                #pragma unroll
                for (int j=0;j<2;j++) MMA_F16(acc[i][j], a[i], bf[j]);
        }
        #pragma unroll
        for (int i=0;i<2;i++){
            int l0 = wm*32 + i*16 + gid;
            float e0 = eacl[l0], e1 = eacl[l0+8];
            #pragma unroll
            for (int j=0;j<2;j++){
                acc[i][j][0] *= e0; acc[i][j][1] *= e0;
                acc[i][j][2] *= e1; acc[i][j][3] *= e1;
            }
        }
        __syncthreads();
    }

    // ---- Y_diag over s-tiles <= lt (C stays in Cb)
    for (int st = 0; st <= lt; st++){
        if (tid < 64){
            acs[tid] = ac[st*64 + tid];
            dts[tid] = g_dt[(size_t)(bb*SEQLEN + c*CHUNK_T + st*64 + tid)*NH + h];
        }
        for (int i2 = tid; i2 < 2048; i2 += 256){
            int r = i2 >> 5, c2 = (i2 & 31) * 2;
            int tgs = c*CHUNK_T + st*64 + r;
            int trs = rev ? (SEQLEN-1 - tgs) : tgs;
            *(__half2*)&Bb[r*SMH + c2] =
                *(const __half2*)&g_xch[(size_t)(b*SEQLEN + trs)*CONVD + DI + c2];
        }
        __syncthreads();
        float g[2][2][4];
        #pragma unroll
        for (int i=0;i<2;i++)
            #pragma unroll
            for (int j=0;j<2;j++)
                #pragma unroll
                for (int r=0;r<4;r++) g[i][j][r]=0.f;
        #pragma unroll
        for (int ks = 0; ks < 64; ks += 16){
            unsigned a[2][4], bf[2][2];
            #pragma unroll
            for (int i=0;i<2;i++)
                ldsm4(a[i], Cb + (wm*32 + i*16 + rowsel)*SMH + ks + koffA);
            {
                unsigned t0[4];
                ldsm4(t0, Bb + (wn*16 + nsel)*SMH + ks + koffB);
                bf[0][0]=t0[0]; bf[0][1]=t0[1]; bf[1][0]=t0[2]; bf[1][1]=t0[3];
            }
            #pragma unroll
            for (int i=0;i<2;i++)
                #pragma unroll
                for (int j=0;j<2;j++) MMA_F16(g[i][j], a[i], bf[j]);
        }
        __syncthreads();
        bool diag = (st == lt);
        #pragma unroll
        for (int i=0;i<2;i++){
            int l0 = wm*32 + i*16 + gid;
            #pragma unroll
            for (int j=0;j<2;j++){
                int s0 = wn*16 + j*8 + 2*qid;
                float al0 = acl[l0], al1 = acl[l0+8];
                float w00 = (diag && s0   > l0) ? 0.f : expf(al0 - acs[s0]);
                float w01 = (diag && s0+1 > l0) ? 0.f : expf(al0 - acs[s0+1]);
                float w10 = (diag && s0   > l0+8) ? 0.f : expf(al1 - acs[s0]);
                float w11 = (diag && s0+1 > l0+8) ? 0.f : expf(al1 - acs[s0+1]);
                *(__half2*)&Ab[l0*SMH + s0] =
                    __floats2half2_rn(g[i][j][0]*w00, g[i][j][1]*w01);
                *(__half2*)&Ab[(l0+8)*SMH + s0] =
                    __floats2half2_rn(g[i][j][2]*w10, g[i][j][3]*w11);
            }
        }
        for (int idx = tid; idx < 64*64; idx += 256){
            int s = idx >> 6, p = idx & 63;
            int tgs = c*CHUNK_T + st*64 + s;
            int trs = rev ? (SEQLEN-1 - tgs) : tgs;
            float xv = __half2float(g_xch[(size_t)(b*SEQLEN + trs)*CONVD + h*HD + p]);
            Bb[p*SMH + s] = __float2half(xv * dts[s]);
        }
        __syncthreads();
        #pragma unroll
        for (int ks = 0; ks < 64; ks += 16){
            unsigned a[2][4], bf[2][2];
            #pragma unroll
            for (int i=0;i<2;i++)
                ldsm4(a[i], Ab + (wm*32 + i*16 + rowsel)*SMH + ks + koffA);
            {
                unsigned t0[4];
                ldsm4(t0, Bb + (wn*16 + nsel)*SMH + ks + koffB);
                bf[0][0]=t0[0]; bf[0][1]=t0[1]; bf[1][0]=t0[2]; bf[1][1]=t0[3];
            }
            #pragma unroll
            for (int i=0;i<2;i++)
                #pragma unroll
                for (int j=0;j<2;j++) MMA_F16(acc[i][j], a[i], bf[j]);
        }
        __syncthreads();
    }

    #pragma unroll
    for (int i=0;i<2;i++){
        int l = wm*32 + i*16 + gid;
        int tg0 = c*CHUNK_T + lt*64 + l;
        #pragma unroll
        for (int j=0;j<2;j++){
            int pc = h*HD + wn*16 + j*8 + 2*qid;
            size_t o0 = (size_t)(bb*SEQLEN + tg0)*DI + pc;
            size_t o1 = (size_t)(bb*SEQLEN + tg0 + 8)*DI + pc;
            *(__half2*)&g_yssdh[o0] = __floats2half2_rn(acc[i][j][0], acc[i][j][1]);
            *(__half2*)&g_yssdh[o1] = __floats2half2_rn(acc[i][j][2], acc[i][j][3]);
        }
    }
}

// ---------------- 9) fc_D (fp16 inputs) ----------------
__global__ void fcd_kernel(const float* __restrict__ fw){
    __shared__ float ws[NH][132];
    int r0 = blockIdx.x * 64;
    int tid = threadIdx.x;
    int rl = tid >> 2;
    int lj = tid & 3;
    float acc[6] = {0.f,0.f,0.f,0.f,0.f,0.f};
    for (int k0 = 0; k0 < DI; k0 += 128){
        for (int i = tid; i < NH*128; i += 256)
            ws[i>>7][i&127] = fw[(size_t)(i>>7)*DI + k0 + (i&127)];
        __syncthreads();
        const __half2* xr = (const __half2*)&g_xch[(size_t)(r0+rl)*CONVD + k0];
        #pragma unroll 16
        for (int kk = 0; kk < 64; kk += 2){
            float2 x0 = __half22float2(xr[kk]);
            float2 x1 = __half22float2(xr[kk+1]);
            #pragma unroll
            for (int hh = 0; hh < 6; hh++){
                int h = lj*6 + hh;
                acc[hh] += x0.x*ws[h][kk*2] + x0.y*ws[h][kk*2+1]
                         + x1.x*ws[h][kk*2+2] + x1.y*ws[h][kk*2+3];
            }
        }
        __syncthreads();
    }
    #pragma unroll
    for (int hh = 0; hh < 6; hh++)
        g_dterm[(size_t)(r0+rl)*NH + lj*6 + hh] = acc[hh];
}

// ---------------- 10) combine + gate + RMSNorm (half2 vectorized) ----------
__global__ void combine_kernel(const float* __restrict__ Dv,
                               const float* __restrict__ rms_w){
    __shared__ float ybuf[DI];
    __shared__ float red[8];
    int bl = blockIdx.x;
    int b = bl / SEQLEN, t = bl % SEQLEN;
    int tid = threadIdx.x;
    float ss = 0.f;
    for (int d = tid*2; d < DI; d += 512){
        float2 yf = make_float2(0.f, 0.f), yb = make_float2(0.f, 0.f);
        if (t > 0)
            yf = __half22float2(*(const __half2*)&g_yssdh[(size_t)(b*SEQLEN + t - 1)*DI + d]);
        if (t <= SEQLEN-2)
            yb = __half22float2(*(const __half2*)&g_yssdh[(size_t)((2+b)*SEQLEN + (SEQLEN-2 - t))*DI + d]);
        float2 xo = __half22float2(*(const __half2*)&g_xch[(size_t)bl*CONVD + d]);
        float2 z  = __half22float2(*(const __half2*)&g_zxh[(size_t)bl*DIP + d]);
        int h = d >> 6;
        float dterm = g_dterm[(size_t)bl*NH + h] + Dv[h];
        float y0 = (yf.x + yb.x + xo.x*dterm) * siluf(z.x);
        float y1 = (yf.y + yb.y + xo.y*dterm) * siluf(z.y);
        ybuf[d] = y0; ybuf[d+1] = y1;
        ss += y0*y0 + y1*y1;
    }
    float tot = blockReduce256(ss, red);
    float inv = rsqrtf(tot/DI + EPSV);
    __syncthreads();
    for (int d = tid*2; d < DI; d += 512){
        float2 rw = *(const float2*)&rms_w[d];
        *(__half2*)&g_ynh[(size_t)bl*DI + d] =
            __floats2half2_rn(ybuf[d]*inv*rw.x, ybuf[d+1]*inv*rw.y);
    }
}

// ---------------- launch ----------------
extern "C" void kernel_launch(void* const* d_in, const int* in_sizes, int n_in,
                              void* d_out, int out_size){
    const float* x          = (const float*)d_in[0];
    const float* ln_w       = (const float*)d_in[1];
    const float* ln_b       = (const float*)d_in[2];
    const float* in_proj_w  = (const float*)d_in[3];
    const float* conv_w     = (const float*)d_in[4];
    const float* conv_b     = (const float*)d_in[5];
    const float* dt_bias    = (const float*)d_in[6];
    const float* A_log      = (const float*)d_in[7];
    const float* Dv         = (const float*)d_in[8];
    const float* fc_D_w     = (const float*)d_in[9];
    const float* rms_w      = (const float*)d_in[10];
    const float* out_proj_w = (const float*)d_in[11];
    float* out = (float*)d_out;

    __half *uh, *ynh, *wah, *woh, *zxh;
    cudaGetSymbolAddress((void**)&uh,  g_uh);
    cudaGetSymbolAddress((void**)&ynh, g_ynh);
    cudaGetSymbolAddress((void**)&wah, g_wah);
    cudaGetSymbolAddress((void**)&woh, g_woh);
    cudaGetSymbolAddress((void**)&zxh, g_zxh);

    static bool attr_set = false;
    const int gsmem   = GSTH*2*128*SMSH*(int)sizeof(__half);       // 81920 B
    const int gsmem64 = GSTH*(128+64)*SMSH*(int)sizeof(__half);    // 61440 B
    if (!attr_set){
        cudaFuncSetAttribute(gemm_h, cudaFuncAttributeMaxDynamicSharedMemorySize, gsmem);
        cudaFuncSetAttribute(gemm_h_n64, cudaFuncAttributeMaxDynamicSharedMemorySize, gsmem64);
        attr_set = true;
    }

    wconv_kernel<<<(DIP*DM + 255)/256, 256>>>(in_proj_w, out_proj_w);
    ln_kernel<<<BL, 256>>>(x, ln_w, ln_b);

    // in_proj -> fp16 zx
    gemm_h<<<dim3((DIP+127)/128, BL/128), 256, gsmem>>>(uh, DM, wah, DM,
        nullptr, nullptr, zxh, DIP, BL, DIP, DM);

    conv_kernel<<<dim3(CONVD/128, SEQLEN/CTS, BATCH), 256>>>(conv_w, conv_b);
    cumsum_kernel<<<NBB*NH*NC, 256>>>(A_log, dt_bias);
    states_kernel<<<NBB*NC*NH, 256>>>();
    prevscan_kernel<<<NBB*NH*4, 256>>>();
    ydiag_kernel<<<NBB*NC*NH*4, 256>>>();
    fcd_kernel<<<BL/64, 256>>>(fc_D_w);
    combine_kernel<<<BL, 256>>>(Dv, rms_w);

    // out_proj + residual -> fp32 out
    gemm_h_n64<<<dim3(DM/64, BL/128), 256, gsmem64>>>(ynh, DI, woh, DI,
        x, out, DM, BL, DM, DI);
}